// round 13
// baseline (speedup 1.0000x reference)
#include <cuda_runtime.h>
#include <cuda_fp16.h>
#include <cstdint>
#include <cstddef>

#define DEV_INLINE __device__ __forceinline__

// B=8, C=64, S=256, WS=32, P=4, HEADS=8, DH=64
constexpr int NTOK = 32768;
constexpr int TOKD = 1024;
constexpr int QKVD = 1536;
constexpr int INNERD = 512;

// ---- static scratch ----
__device__ __half g_tokens[(size_t)NTOK * TOKD];            // [token][k]
__device__ __half g_qkv[(size_t)NTOK * QKVD];               // [token][f]
__device__ __half g_o[(size_t)NTOK * INNERD];               // [token][e]
__device__ uint32_t g_wqkv[(size_t)QKVD * (TOKD / 2)];      // [f][k2]  half2-packed
__device__ uint32_t g_wout[(size_t)TOKD * (INNERD / 2)];    // [dp][e2] half2-packed
__device__ float g_bias[TOKD];

DEV_INLINE void mma16(float* d, const uint32_t* a, const uint32_t* b) {
    asm volatile("mma.sync.aligned.m16n8k16.row.col.f32.f16.f16.f32 "
        "{%0,%1,%2,%3}, {%4,%5,%6,%7}, {%8,%9}, {%0,%1,%2,%3};"
        : "+f"(d[0]), "+f"(d[1]), "+f"(d[2]), "+f"(d[3])
        : "r"(a[0]), "r"(a[1]), "r"(a[2]), "r"(a[3]), "r"(b[0]), "r"(b[1]));
}
DEV_INLINE void cp16(const void* dst, const void* src) {
    uint32_t a = (uint32_t)__cvta_generic_to_shared(dst);
    asm volatile("cp.async.ca.shared.global [%0], [%1], 16;" :: "r"(a), "l"(src));
}
DEV_INLINE void ldsm4(uint32_t* r, uint32_t addr) {
    asm volatile("ldmatrix.sync.aligned.m8n8.x4.shared.b16 {%0,%1,%2,%3}, [%4];"
        : "=r"(r[0]), "=r"(r[1]), "=r"(r[2]), "=r"(r[3]) : "r"(addr));
}
DEV_INLINE void ldsm4t(uint32_t* r, uint32_t addr) {
    asm volatile("ldmatrix.sync.aligned.m8n8.x4.trans.shared.b16 {%0,%1,%2,%3}, [%4];"
        : "=r"(r[0]), "=r"(r[1]), "=r"(r[2]), "=r"(r[3]) : "r"(addr));
}
DEV_INLINE uint32_t h2u(__half2 h) { return *(uint32_t*)&h; }

// ---- weight prep: d' = c*16 + p1*4 + p2 ; src d = (p1*4+p2)*64 + c ----
__global__ void perm_wqkv_k(const float* __restrict__ w) {
    __shared__ uint32_t sm[32][33];
    int k20 = blockIdx.x * 32, f0 = blockIdx.y * 32;
    int tx = threadIdx.x, ty = threadIdx.y;     // (32, 8)
#pragma unroll
    for (int i = 0; i < 4; i++) {
        int k2l = ty + i * 8;
        int d0 = 2 * (k20 + k2l), d1 = d0 + 1;
        int s0 = (d0 & 15) * 64 + (d0 >> 4);
        int s1 = (d1 & 15) * 64 + (d1 >> 4);
        sm[k2l][tx] = h2u(__floats2half2_rn(w[(size_t)s0 * QKVD + f0 + tx],
                                            w[(size_t)s1 * QKVD + f0 + tx]));
    }
    __syncthreads();
#pragma unroll
    for (int i = 0; i < 4; i++) {
        int fl = ty + i * 8;
        g_wqkv[(size_t)(f0 + fl) * (TOKD / 2) + k20 + tx] = sm[tx][fl];
    }
}
__global__ void perm_wout_k(const float* __restrict__ w, const float* __restrict__ b) {
    __shared__ uint32_t sm[32][33];
    int e20 = blockIdx.x * 32, d0 = blockIdx.y * 32;
    int tx = threadIdx.x, ty = threadIdx.y;     // (32, 8)
#pragma unroll
    for (int i = 0; i < 4; i++) {
        int e2l = ty + i * 8;
        int e = 2 * (e20 + e2l);
        sm[e2l][tx] = h2u(__floats2half2_rn(w[(size_t)e * TOKD + d0 + tx],
                                            w[(size_t)(e + 1) * TOKD + d0 + tx]));
    }
    __syncthreads();
#pragma unroll
    for (int i = 0; i < 4; i++) {
        int dl = ty + i * 8;
        int d = d0 + dl;
        int dp = (d & 63) * 16 + (d >> 6);
        g_wout[(size_t)dp * (INNERD / 2) + e20 + tx] = sm[tx][dl];
    }
    if (blockIdx.x == 0 && ty == 0) {
        int d = d0 + tx;
        g_bias[(d & 63) * 16 + (d >> 6)] = b[d];
    }
}

// ---- gather: x[b,c,h,w] -> g_tokens[win*64+t][d'] (fp16) ----
__global__ void gather_k(const float* __restrict__ x) {
    int blk = blockIdx.x;
    int b = blk >> 8, h = blk & 255;
    int tid = threadIdx.x;               // 256
    int w4 = tid & 63, c0 = tid >> 6;
    int h1 = h >> 5, hh = h & 31, nh_i = hh >> 2, p1 = hh & 3;
    int w1 = w4 >> 3, nw_j = w4 & 7;
    int win = b * 64 + h1 * 8 + w1;
    int t = nh_i * 8 + nw_j;
    size_t drow = ((size_t)win * 64 + t) * TOKD + p1 * 4;
    size_t sbase = (((size_t)b * 64) * 256 + h) * 256 + w4 * 4;
#pragma unroll
    for (int i = 0; i < 16; i++) {
        int c = c0 * 16 + i;
        float4 v = *(const float4*)&x[sbase + (size_t)c * 65536];
        uint2 o;
        o.x = h2u(__floats2half2_rn(v.x, v.y));
        o.y = h2u(__floats2half2_rn(v.z, v.w));
        *(uint2*)&g_tokens[drow + (size_t)c * 16] = o;
    }
}

// ---- fp16 GEMM: 128x128 CTA, 2x2 warps of 64x64, K-step 64, 3-stage ----
// stage (36864 B): A [128][72] half (18432) | B [128][36] u32 (18432)
constexpr int STG = 36864;
constexpr int GEMM_SMEM = 3 * STG;   // 110592
template<int K, int N, int MODE>
__global__ void __launch_bounds__(128, 2) gemm_fp16_k(float* __restrict__ outp) {
    extern __shared__ char smem_raw[];
    const uint32_t sb = (uint32_t)__cvta_generic_to_shared(smem_raw);

    const __half* A = (MODE == 0) ? g_tokens : g_o;
    const uint32_t* Bp = (MODE == 0) ? g_wqkv : g_wout;
    constexpr int K2 = K / 2;

    const int tid = threadIdx.x, warp = tid >> 5, lane = tid & 31;
    const int wm = warp >> 1, wn = warp & 1;
    const int tm = blockIdx.y * 128, tn = blockIdx.x * 128;
    const int r0 = lane >> 2;

    float acc[4][8][4];
#pragma unroll
    for (int mi = 0; mi < 4; mi++)
#pragma unroll
        for (int ni = 0; ni < 8; ni++)
#pragma unroll
            for (int j = 0; j < 4; j++) acc[mi][ni][j] = 0.f;

    constexpr int KT = K / 64;
    const int lr = tid >> 3, lc = tid & 7;   // load row/chunk

    auto load_stage = [&](int kt) {
        const int st = kt % 3;
        const int k0 = kt * 64, k20 = kt * 32;
        __half* As = (__half*)(smem_raw + st * STG);
        uint32_t* Bs = (uint32_t*)(smem_raw + st * STG + 18432);
#pragma unroll
        for (int i = 0; i < 8; i++) {
            int r = lr + i * 16;
            cp16(&As[r * 72 + lc * 8], &A[(size_t)(tm + r) * K + k0 + lc * 8]);
        }
#pragma unroll
        for (int i = 0; i < 8; i++) {
            int r = lr + i * 16;
            cp16(&Bs[r * 36 + lc * 4], &Bp[(size_t)(tn + r) * K2 + k20 + lc * 4]);
        }
        asm volatile("cp.async.commit_group;");
    };

    load_stage(0); load_stage(1);

    const uint32_t a_lane = ((wm * 64 + (lane & 15)) * 72 + (lane >> 4) * 8) * 2;
    const uint32_t b_lane = 18432 + ((wn * 64 + (lane >> 4) * 8 + (lane & 7)) * 36
                             + ((lane >> 3) & 1) * 4) * 4;

    for (int kt = 0; kt < KT; kt++) {
        if (kt + 1 < KT) {
            asm volatile("cp.async.wait_group 1;");
        } else {
            asm volatile("cp.async.wait_group 0;");
        }
        __syncthreads();
        if (kt + 2 < KT) load_stage(kt + 2);
        const uint32_t stb = sb + (kt % 3) * STG;
        const uint32_t abuf = stb + a_lane;
        const uint32_t bbuf = stb + b_lane;
#pragma unroll
        for (int ks = 0; ks < 4; ks++) {
            uint32_t a[4][4], bq[8][2];
#pragma unroll
            for (int mi = 0; mi < 4; mi++)
                ldsm4(a[mi], abuf + mi * 2304 + ks * 32);
#pragma unroll
            for (int p = 0; p < 4; p++) {
                uint32_t t4[4];
                ldsm4(t4, bbuf + p * 2304 + ks * 32);
                bq[2 * p][0] = t4[0]; bq[2 * p][1] = t4[1];
                bq[2 * p + 1][0] = t4[2]; bq[2 * p + 1][1] = t4[3];
            }
#pragma unroll
            for (int mi = 0; mi < 4; mi++)
#pragma unroll
                for (int ni = 0; ni < 8; ni++)
                    mma16(acc[mi][ni], a[mi], bq[ni]);
        }
    }
    const int c2 = (lane & 3) * 2;
#pragma unroll
    for (int mi = 0; mi < 4; mi++) {
#pragma unroll
        for (int ni = 0; ni < 8; ni++) {
            int row = tm + wm * 64 + mi * 16 + r0;
            int col = tn + wn * 64 + ni * 8 + c2;
            if (MODE == 0) {
                *(uint32_t*)&g_qkv[(size_t)row * N + col] =
                    h2u(__floats2half2_rn(acc[mi][ni][0], acc[mi][ni][1]));
                *(uint32_t*)&g_qkv[(size_t)(row + 8) * N + col] =
                    h2u(__floats2half2_rn(acc[mi][ni][2], acc[mi][ni][3]));
            } else {
                int win = row >> 6, t = row & 63;
                int b = win >> 6, rem = win & 63;
                size_t cterm = (size_t)(col >> 4) << 16;
                float b0 = g_bias[col], b1 = g_bias[col + 1];
                size_t xr = ((size_t)(b * 64) << 16)
                          + ((size_t)(((rem >> 3) << 5) | ((t >> 3) << 2) | ((col >> 2) & 3)) << 8)
                          + (size_t)(((rem & 7) << 5) | ((t & 7) << 2) | (col & 3));
                *(float2*)&outp[xr + cterm] =
                    make_float2(acc[mi][ni][0] + b0, acc[mi][ni][1] + b1);
                int t8 = t + 8;
                size_t xr8 = ((size_t)(b * 64) << 16)
                           + ((size_t)(((rem >> 3) << 5) | ((t8 >> 3) << 2) | ((col >> 2) & 3)) << 8)
                           + (size_t)(((rem & 7) << 5) | ((t8 & 7) << 2) | (col & 3));
                *(float2*)&outp[xr8 + cterm] =
                    make_float2(acc[mi][ni][2] + b0, acc[mi][ni][3] + b1);
            }
        }
    }
}

// ---- attention: CTA = (window, head), 1 warp, tensor-core S and PV ----
__global__ void __launch_bounds__(32) attn_k() {
    __shared__ __half Qs[64 * 72];       // 9216 B, rows stride 144 B
    __shared__ uint32_t Ksm[64 * 36];    // 9216 B, k2-packed, stride 144 B
    __shared__ __half Vs[64 * 72];       // 9216 B
    const int win = blockIdx.y, hd = blockIdx.x, lane = threadIdx.x;
    const __half* base = g_qkv + (size_t)win * 64 * QKVD + hd * 64;
    const __half2 sc = __floats2half2_rn(0.125f, 0.125f);

#pragma unroll
    for (int i = 0; i < 16; i++) {
        int idx = i * 32 + lane;
        int r = idx >> 3, c8 = idx & 7;
        const __half* rp = base + (size_t)r * QKVD;
        uint4 q4 = *(const uint4*)(rp + c8 * 8);
        __half2* qh = (__half2*)&q4;
        qh[0] = __hmul2(qh[0], sc); qh[1] = __hmul2(qh[1], sc);
        qh[2] = __hmul2(qh[2], sc); qh[3] = __hmul2(qh[3], sc);
        *(uint4*)&Qs[r * 72 + c8 * 8] = q4;
        *(uint4*)&Ksm[r * 36 + c8 * 4] = *(const uint4*)(rp + INNERD + c8 * 8);
        *(uint4*)&Vs[r * 72 + c8 * 8] = *(const uint4*)(rp + 2 * INNERD + c8 * 8);
    }
    __syncwarp();

    const uint32_t sbQ = (uint32_t)__cvta_generic_to_shared(Qs);
    const uint32_t sbK = (uint32_t)__cvta_generic_to_shared(Ksm);
    const uint32_t sbV = (uint32_t)__cvta_generic_to_shared(Vs);

    uint32_t a[4][4][4];
#pragma unroll
    for (int mi = 0; mi < 4; mi++)
#pragma unroll
        for (int ks = 0; ks < 4; ks++)
            ldsm4(a[mi][ks],
                  sbQ + ((mi * 16 + (lane & 15)) * 72 + ks * 16 + (lane >> 4) * 8) * 2);

    float s[4][8][4];
#pragma unroll
    for (int mi = 0; mi < 4; mi++)
#pragma unroll
        for (int ni = 0; ni < 8; ni++)
#pragma unroll
            for (int j = 0; j < 4; j++) s[mi][ni][j] = 0.f;
    const uint32_t kl = sbK + ((lane >> 4) * 8 + (lane & 7)) * 144 + ((lane >> 3) & 1) * 16;
#pragma unroll
    for (int ks = 0; ks < 4; ks++) {
#pragma unroll
        for (int p = 0; p < 4; p++) {
            uint32_t t4[4];
            ldsm4(t4, kl + p * 2304 + ks * 32);
#pragma unroll
            for (int mi = 0; mi < 4; mi++) {
                mma16(s[mi][2 * p], a[mi][ks], t4);
                mma16(s[mi][2 * p + 1], a[mi][ks], t4 + 2);
            }
        }
    }

    float inv0[4], inv1[4];
#pragma unroll
    for (int mi = 0; mi < 4; mi++) {
        float m0 = -1e30f, m1 = -1e30f;
#pragma unroll
        for (int ni = 0; ni < 8; ni++) {
            m0 = fmaxf(m0, fmaxf(s[mi][ni][0], s[mi][ni][1]));
            m1 = fmaxf(m1, fmaxf(s[mi][ni][2], s[mi][ni][3]));
        }
        m0 = fmaxf(m0, __shfl_xor_sync(0xffffffff, m0, 1));
        m0 = fmaxf(m0, __shfl_xor_sync(0xffffffff, m0, 2));
        m1 = fmaxf(m1, __shfl_xor_sync(0xffffffff, m1, 1));
        m1 = fmaxf(m1, __shfl_xor_sync(0xffffffff, m1, 2));
        float s0 = 0.f, s1 = 0.f;
#pragma unroll
        for (int ni = 0; ni < 8; ni++) {
            s[mi][ni][0] = __expf(s[mi][ni][0] - m0);
            s[mi][ni][1] = __expf(s[mi][ni][1] - m0);
            s[mi][ni][2] = __expf(s[mi][ni][2] - m1);
            s[mi][ni][3] = __expf(s[mi][ni][3] - m1);
            s0 += s[mi][ni][0] + s[mi][ni][1];
            s1 += s[mi][ni][2] + s[mi][ni][3];
        }
        s0 += __shfl_xor_sync(0xffffffff, s0, 1);
        s0 += __shfl_xor_sync(0xffffffff, s0, 2);
        s1 += __shfl_xor_sync(0xffffffff, s1, 1);
        s1 += __shfl_xor_sync(0xffffffff, s1, 2);
        inv0[mi] = 1.f / s0; inv1[mi] = 1.f / s1;
    }

    uint32_t pa[4][4][4];
#pragma unroll
    for (int mi = 0; mi < 4; mi++)
#pragma unroll
        for (int ks = 0; ks < 4; ks++) {
            pa[mi][ks][0] = h2u(__floats2half2_rn(s[mi][2 * ks][0], s[mi][2 * ks][1]));
            pa[mi][ks][1] = h2u(__floats2half2_rn(s[mi][2 * ks][2], s[mi][2 * ks][3]));
            pa[mi][ks][2] = h2u(__floats2half2_rn(s[mi][2 * ks + 1][0], s[mi][2 * ks + 1][1]));
            pa[mi][ks][3] = h2u(__floats2half2_rn(s[mi][2 * ks + 1][2], s[mi][2 * ks + 1][3]));
        }

    float o[4][8][4];
#pragma unroll
    for (int mi = 0; mi < 4; mi++)
#pragma unroll
        for (int ni = 0; ni < 8; ni++)
#pragma unroll
            for (int j = 0; j < 4; j++) o[mi][ni][j] = 0.f;
    const uint32_t vl = sbV + ((lane & 15) * 72 + (lane >> 4) * 8) * 2;
#pragma unroll
    for (int ks = 0; ks < 4; ks++) {
#pragma unroll
        for (int nd = 0; nd < 4; nd++) {
            uint32_t t4[4];
            ldsm4t(t4, vl + ks * 2304 + nd * 32);
#pragma unroll
            for (int mi = 0; mi < 4; mi++) {
                mma16(o[mi][2 * nd], pa[mi][ks], t4);
                mma16(o[mi][2 * nd + 1], pa[mi][ks], t4 + 2);
            }
        }
    }

    __half* ob = g_o + (size_t)win * 64 * INNERD + hd * 64;
#pragma unroll
    for (int mi = 0; mi < 4; mi++) {
        int r = mi * 16 + (lane >> 2);
#pragma unroll
        for (int ni = 0; ni < 8; ni++) {
            int col = ni * 8 + (lane & 3) * 2;
            *(__half2*)&ob[(size_t)r * INNERD + col] =
                __floats2half2_rn(o[mi][ni][0] * inv0[mi], o[mi][ni][1] * inv0[mi]);
            *(__half2*)&ob[(size_t)(r + 8) * INNERD + col] =
                __floats2half2_rn(o[mi][ni][2] * inv1[mi], o[mi][ni][3] * inv1[mi]);
        }
    }
}

extern "C" void kernel_launch(void* const* d_in, const int* in_sizes, int n_in,
                              void* d_out, int out_size) {
    const float* x     = (const float*)d_in[0];
    const float* w_qkv = (const float*)d_in[1];
    const float* w_out = (const float*)d_in[2];
    const float* b_out = (const float*)d_in[3];
    float* out = (float*)d_out;

    cudaFuncSetAttribute(gemm_fp16_k<TOKD, QKVD, 0>,
                         cudaFuncAttributeMaxDynamicSharedMemorySize, GEMM_SMEM);
    cudaFuncSetAttribute(gemm_fp16_k<INNERD, TOKD, 1>,
                         cudaFuncAttributeMaxDynamicSharedMemorySize, GEMM_SMEM);

    perm_wqkv_k<<<dim3(TOKD / 64, QKVD / 32), dim3(32, 8)>>>(w_qkv);
    perm_wout_k<<<dim3(INNERD / 64, TOKD / 32), dim3(32, 8)>>>(w_out, b_out);
    gather_k<<<2048, 256>>>(x);
    gemm_fp16_k<TOKD, QKVD, 0>
        <<<dim3(QKVD / 128, NTOK / 128), 128, GEMM_SMEM>>>(nullptr);
    attn_k<<<dim3(8, 512), 32>>>();
    gemm_fp16_k<INNERD, TOKD, 1>
        <<<dim3(TOKD / 128, NTOK / 128), 128, GEMM_SMEM>>>(out);
}

// round 14
// speedup vs baseline: 1.1529x; 1.1529x over previous
#include <cuda_runtime.h>
#include <cuda_fp16.h>
#include <cstdint>
#include <cstddef>

#define DEV_INLINE __device__ __forceinline__

// B=8, C=64, S=256, WS=32, P=4, HEADS=8, DH=64
constexpr int NTOK = 32768;
constexpr int TOKD = 1024;
constexpr int QKVD = 1536;
constexpr int INNERD = 512;

// ---- static scratch ----
__device__ __half g_tokens[(size_t)NTOK * TOKD];            // [token][k]
__device__ __half g_qkv[(size_t)NTOK * QKVD];               // [token][f]
__device__ __half g_o[(size_t)NTOK * INNERD];               // [token][e]
__device__ uint32_t g_wqkv[(size_t)QKVD * (TOKD / 2)];      // [f][k2]  half2-packed
__device__ uint32_t g_wout[(size_t)TOKD * (INNERD / 2)];    // [dp][e2] half2-packed
__device__ float g_bias[TOKD];

DEV_INLINE void mma16(float* d, const uint32_t* a, const uint32_t* b) {
    asm volatile("mma.sync.aligned.m16n8k16.row.col.f32.f16.f16.f32 "
        "{%0,%1,%2,%3}, {%4,%5,%6,%7}, {%8,%9}, {%0,%1,%2,%3};"
        : "+f"(d[0]), "+f"(d[1]), "+f"(d[2]), "+f"(d[3])
        : "r"(a[0]), "r"(a[1]), "r"(a[2]), "r"(a[3]), "r"(b[0]), "r"(b[1]));
}
DEV_INLINE void cp16(const void* dst, const void* src) {
    uint32_t a = (uint32_t)__cvta_generic_to_shared(dst);
    asm volatile("cp.async.ca.shared.global [%0], [%1], 16;" :: "r"(a), "l"(src));
}
DEV_INLINE void ldsm4(uint32_t* r, uint32_t addr) {
    asm volatile("ldmatrix.sync.aligned.m8n8.x4.shared.b16 {%0,%1,%2,%3}, [%4];"
        : "=r"(r[0]), "=r"(r[1]), "=r"(r[2]), "=r"(r[3]) : "r"(addr));
}
DEV_INLINE void ldsm4t(uint32_t* r, uint32_t addr) {
    asm volatile("ldmatrix.sync.aligned.m8n8.x4.trans.shared.b16 {%0,%1,%2,%3}, [%4];"
        : "=r"(r[0]), "=r"(r[1]), "=r"(r[2]), "=r"(r[3]) : "r"(addr));
}
DEV_INLINE uint32_t h2u(__half2 h) { return *(uint32_t*)&h; }

// ---- weight prep: d' = c*16 + p1*4 + p2 ; src d = (p1*4+p2)*64 + c ----
__global__ void perm_wqkv_k(const float* __restrict__ w) {
    __shared__ uint32_t sm[32][33];
    int k20 = blockIdx.x * 32, f0 = blockIdx.y * 32;
    int tx = threadIdx.x, ty = threadIdx.y;     // (32, 8)
#pragma unroll
    for (int i = 0; i < 4; i++) {
        int k2l = ty + i * 8;
        int d0 = 2 * (k20 + k2l), d1 = d0 + 1;
        int s0 = (d0 & 15) * 64 + (d0 >> 4);
        int s1 = (d1 & 15) * 64 + (d1 >> 4);
        sm[k2l][tx] = h2u(__floats2half2_rn(w[(size_t)s0 * QKVD + f0 + tx],
                                            w[(size_t)s1 * QKVD + f0 + tx]));
    }
    __syncthreads();
#pragma unroll
    for (int i = 0; i < 4; i++) {
        int fl = ty + i * 8;
        g_wqkv[(size_t)(f0 + fl) * (TOKD / 2) + k20 + tx] = sm[tx][fl];
    }
}
__global__ void perm_wout_k(const float* __restrict__ w, const float* __restrict__ b) {
    __shared__ uint32_t sm[32][33];
    int e20 = blockIdx.x * 32, d0 = blockIdx.y * 32;
    int tx = threadIdx.x, ty = threadIdx.y;     // (32, 8)
#pragma unroll
    for (int i = 0; i < 4; i++) {
        int e2l = ty + i * 8;
        int e = 2 * (e20 + e2l);
        sm[e2l][tx] = h2u(__floats2half2_rn(w[(size_t)e * TOKD + d0 + tx],
                                            w[(size_t)(e + 1) * TOKD + d0 + tx]));
    }
    __syncthreads();
#pragma unroll
    for (int i = 0; i < 4; i++) {
        int dl = ty + i * 8;
        int d = d0 + dl;
        int dp = (d & 63) * 16 + (d >> 6);
        g_wout[(size_t)dp * (INNERD / 2) + e20 + tx] = sm[tx][dl];
    }
    if (blockIdx.x == 0 && ty == 0) {
        int d = d0 + tx;
        g_bias[(d & 63) * 16 + (d >> 6)] = b[d];
    }
}

// ---- gather: x[b,c,h,w] -> g_tokens[win*64+t][d'] (fp16) ----
__global__ void gather_k(const float* __restrict__ x) {
    int blk = blockIdx.x;
    int b = blk >> 8, h = blk & 255;
    int tid = threadIdx.x;               // 256
    int w4 = tid & 63, c0 = tid >> 6;
    int h1 = h >> 5, hh = h & 31, nh_i = hh >> 2, p1 = hh & 3;
    int w1 = w4 >> 3, nw_j = w4 & 7;
    int win = b * 64 + h1 * 8 + w1;
    int t = nh_i * 8 + nw_j;
    size_t drow = ((size_t)win * 64 + t) * TOKD + p1 * 4;
    size_t sbase = (((size_t)b * 64) * 256 + h) * 256 + w4 * 4;
#pragma unroll
    for (int i = 0; i < 16; i++) {
        int c = c0 * 16 + i;
        float4 v = *(const float4*)&x[sbase + (size_t)c * 65536];
        uint2 o;
        o.x = h2u(__floats2half2_rn(v.x, v.y));
        o.y = h2u(__floats2half2_rn(v.z, v.w));
        *(uint2*)&g_tokens[drow + (size_t)c * 16] = o;
    }
}

// ---- fp16 GEMM: 128x128 CTA, 2x2 warps of 64x64, K-step 64, double-buffered ----
// (round-9 measured-best structure: load(kt+1) -> wait 1 -> sync -> compute -> sync)
// dynamic smem: A [2][128*72] half (36864B) | B [2][128*36] u32 (36864B)
constexpr int GEMM_SMEM = 73728;
template<int K, int N, int MODE>
__global__ void __launch_bounds__(128, 2) gemm_fp16_k(float* __restrict__ outp) {
    extern __shared__ char smem_raw[];
    __half* Asm = (__half*)smem_raw;
    uint32_t* Bsm = (uint32_t*)(smem_raw + 36864);
    const uint32_t sb = (uint32_t)__cvta_generic_to_shared(smem_raw);

    const __half* A = (MODE == 0) ? g_tokens : g_o;
    const uint32_t* Bp = (MODE == 0) ? g_wqkv : g_wout;
    constexpr int K2 = K / 2;

    const int tid = threadIdx.x, warp = tid >> 5, lane = tid & 31;
    const int wm = warp >> 1, wn = warp & 1;
    const int tm = blockIdx.y * 128, tn = blockIdx.x * 128;
    const int r0 = lane >> 2;

    float acc[4][8][4];
#pragma unroll
    for (int mi = 0; mi < 4; mi++)
#pragma unroll
        for (int ni = 0; ni < 8; ni++)
#pragma unroll
            for (int j = 0; j < 4; j++) acc[mi][ni][j] = 0.f;

    constexpr int KT = K / 64;
    const int lr = tid >> 3, lc = tid & 7;   // load row/chunk

    auto load_stage = [&](int kt, int bf) {
        const int k0 = kt * 64, k20 = kt * 32;
#pragma unroll
        for (int i = 0; i < 8; i++) {
            int r = lr + i * 16;
            cp16(&Asm[bf * 9216 + r * 72 + lc * 8], &A[(size_t)(tm + r) * K + k0 + lc * 8]);
        }
#pragma unroll
        for (int i = 0; i < 8; i++) {
            int r = lr + i * 16;
            cp16(&Bsm[bf * 4608 + r * 36 + lc * 4], &Bp[(size_t)(tn + r) * K2 + k20 + lc * 4]);
        }
        asm volatile("cp.async.commit_group;");
    };

    load_stage(0, 0);

    // per-lane ldmatrix base offsets
    const uint32_t a_lane = ((wm * 64 + (lane & 15)) * 72 + (lane >> 4) * 8) * 2;
    const uint32_t b_lane = ((wn * 64 + (lane >> 4) * 8 + (lane & 7)) * 36
                             + ((lane >> 3) & 1) * 4) * 4;

    for (int kt = 0; kt < KT; kt++) {
        if (kt + 1 < KT) {
            load_stage(kt + 1, (kt + 1) & 1);
            asm volatile("cp.async.wait_group 1;");
        } else {
            asm volatile("cp.async.wait_group 0;");
        }
        __syncthreads();
        const uint32_t abuf = sb + (kt & 1) * 18432 + a_lane;
        const uint32_t bbuf = sb + 36864 + (kt & 1) * 18432 + b_lane;
#pragma unroll
        for (int ks = 0; ks < 4; ks++) {
            uint32_t a[4][4], bq[8][2];
#pragma unroll
            for (int mi = 0; mi < 4; mi++)
                ldsm4(a[mi], abuf + mi * 2304 + ks * 32);
#pragma unroll
            for (int p = 0; p < 4; p++) {
                uint32_t t4[4];
                ldsm4(t4, bbuf + p * 2304 + ks * 32);
                bq[2 * p][0] = t4[0]; bq[2 * p][1] = t4[1];
                bq[2 * p + 1][0] = t4[2]; bq[2 * p + 1][1] = t4[3];
            }
#pragma unroll
            for (int mi = 0; mi < 4; mi++)
#pragma unroll
                for (int ni = 0; ni < 8; ni++)
                    mma16(acc[mi][ni], a[mi], bq[ni]);
        }
        __syncthreads();
    }
    const int c2 = (lane & 3) * 2;
#pragma unroll
    for (int mi = 0; mi < 4; mi++) {
#pragma unroll
        for (int ni = 0; ni < 8; ni++) {
            int row = tm + wm * 64 + mi * 16 + r0;
            int col = tn + wn * 64 + ni * 8 + c2;
            if (MODE == 0) {
                *(uint32_t*)&g_qkv[(size_t)row * N + col] =
                    h2u(__floats2half2_rn(acc[mi][ni][0], acc[mi][ni][1]));
                *(uint32_t*)&g_qkv[(size_t)(row + 8) * N + col] =
                    h2u(__floats2half2_rn(acc[mi][ni][2], acc[mi][ni][3]));
            } else {
                int win = row >> 6, t = row & 63;
                int b = win >> 6, rem = win & 63;
                size_t cterm = (size_t)(col >> 4) << 16;
                float b0 = g_bias[col], b1 = g_bias[col + 1];
                size_t xr = ((size_t)(b * 64) << 16)
                          + ((size_t)(((rem >> 3) << 5) | ((t >> 3) << 2) | ((col >> 2) & 3)) << 8)
                          + (size_t)(((rem & 7) << 5) | ((t & 7) << 2) | (col & 3));
                *(float2*)&outp[xr + cterm] =
                    make_float2(acc[mi][ni][0] + b0, acc[mi][ni][1] + b1);
                int t8 = t + 8;
                size_t xr8 = ((size_t)(b * 64) << 16)
                           + ((size_t)(((rem >> 3) << 5) | ((t8 >> 3) << 2) | ((col >> 2) & 3)) << 8)
                           + (size_t)(((rem & 7) << 5) | ((t8 & 7) << 2) | (col & 3));
                *(float2*)&outp[xr8 + cterm] =
                    make_float2(acc[mi][ni][2] + b0, acc[mi][ni][3] + b1);
            }
        }
    }
}

// ---- attention: CTA = (window, head), 1 warp, tensor-core S and PV ----
__global__ void __launch_bounds__(32) attn_k() {
    __shared__ __half Qs[64 * 72];       // 9216 B, rows stride 144 B
    __shared__ uint32_t Ksm[64 * 36];    // 9216 B, k2-packed, stride 144 B
    __shared__ __half Vs[64 * 72];       // 9216 B
    const int win = blockIdx.y, hd = blockIdx.x, lane = threadIdx.x;
    const __half* base = g_qkv + (size_t)win * 64 * QKVD + hd * 64;
    const __half2 sc = __floats2half2_rn(0.125f, 0.125f);

#pragma unroll
    for (int i = 0; i < 16; i++) {
        int idx = i * 32 + lane;
        int r = idx >> 3, c8 = idx & 7;
        const __half* rp = base + (size_t)r * QKVD;
        uint4 q4 = *(const uint4*)(rp + c8 * 8);
        __half2* qh = (__half2*)&q4;
        qh[0] = __hmul2(qh[0], sc); qh[1] = __hmul2(qh[1], sc);
        qh[2] = __hmul2(qh[2], sc); qh[3] = __hmul2(qh[3], sc);
        *(uint4*)&Qs[r * 72 + c8 * 8] = q4;
        *(uint4*)&Ksm[r * 36 + c8 * 4] = *(const uint4*)(rp + INNERD + c8 * 8);
        *(uint4*)&Vs[r * 72 + c8 * 8] = *(const uint4*)(rp + 2 * INNERD + c8 * 8);
    }
    __syncwarp();

    const uint32_t sbQ = (uint32_t)__cvta_generic_to_shared(Qs);
    const uint32_t sbK = (uint32_t)__cvta_generic_to_shared(Ksm);
    const uint32_t sbV = (uint32_t)__cvta_generic_to_shared(Vs);

    uint32_t a[4][4][4];
#pragma unroll
    for (int mi = 0; mi < 4; mi++)
#pragma unroll
        for (int ks = 0; ks < 4; ks++)
            ldsm4(a[mi][ks],
                  sbQ + ((mi * 16 + (lane & 15)) * 72 + ks * 16 + (lane >> 4) * 8) * 2);

    float s[4][8][4];
#pragma unroll
    for (int mi = 0; mi < 4; mi++)
#pragma unroll
        for (int ni = 0; ni < 8; ni++)
#pragma unroll
            for (int j = 0; j < 4; j++) s[mi][ni][j] = 0.f;
    const uint32_t kl = sbK + ((lane >> 4) * 8 + (lane & 7)) * 144 + ((lane >> 3) & 1) * 16;
#pragma unroll
    for (int ks = 0; ks < 4; ks++) {
#pragma unroll
        for (int p = 0; p < 4; p++) {
            uint32_t t4[4];
            ldsm4(t4, kl + p * 2304 + ks * 32);
#pragma unroll
            for (int mi = 0; mi < 4; mi++) {
                mma16(s[mi][2 * p], a[mi][ks], t4);
                mma16(s[mi][2 * p + 1], a[mi][ks], t4 + 2);
            }
        }
    }

    float inv0[4], inv1[4];
#pragma unroll
    for (int mi = 0; mi < 4; mi++) {
        float m0 = -1e30f, m1 = -1e30f;
#pragma unroll
        for (int ni = 0; ni < 8; ni++) {
            m0 = fmaxf(m0, fmaxf(s[mi][ni][0], s[mi][ni][1]));
            m1 = fmaxf(m1, fmaxf(s[mi][ni][2], s[mi][ni][3]));
        }
        m0 = fmaxf(m0, __shfl_xor_sync(0xffffffff, m0, 1));
        m0 = fmaxf(m0, __shfl_xor_sync(0xffffffff, m0, 2));
        m1 = fmaxf(m1, __shfl_xor_sync(0xffffffff, m1, 1));
        m1 = fmaxf(m1, __shfl_xor_sync(0xffffffff, m1, 2));
        float s0 = 0.f, s1 = 0.f;
#pragma unroll
        for (int ni = 0; ni < 8; ni++) {
            s[mi][ni][0] = __expf(s[mi][ni][0] - m0);
            s[mi][ni][1] = __expf(s[mi][ni][1] - m0);
            s[mi][ni][2] = __expf(s[mi][ni][2] - m1);
            s[mi][ni][3] = __expf(s[mi][ni][3] - m1);
            s0 += s[mi][ni][0] + s[mi][ni][1];
            s1 += s[mi][ni][2] + s[mi][ni][3];
        }
        s0 += __shfl_xor_sync(0xffffffff, s0, 1);
        s0 += __shfl_xor_sync(0xffffffff, s0, 2);
        s1 += __shfl_xor_sync(0xffffffff, s1, 1);
        s1 += __shfl_xor_sync(0xffffffff, s1, 2);
        inv0[mi] = 1.f / s0; inv1[mi] = 1.f / s1;
    }

    uint32_t pa[4][4][4];
#pragma unroll
    for (int mi = 0; mi < 4; mi++)
#pragma unroll
        for (int ks = 0; ks < 4; ks++) {
            pa[mi][ks][0] = h2u(__floats2half2_rn(s[mi][2 * ks][0], s[mi][2 * ks][1]));
            pa[mi][ks][1] = h2u(__floats2half2_rn(s[mi][2 * ks][2], s[mi][2 * ks][3]));
            pa[mi][ks][2] = h2u(__floats2half2_rn(s[mi][2 * ks + 1][0], s[mi][2 * ks + 1][1]));
            pa[mi][ks][3] = h2u(__floats2half2_rn(s[mi][2 * ks + 1][2], s[mi][2 * ks + 1][3]));
        }

    float o[4][8][4];
#pragma unroll
    for (int mi = 0; mi < 4; mi++)
#pragma unroll
        for (int ni = 0; ni < 8; ni++)
#pragma unroll
            for (int j = 0; j < 4; j++) o[mi][ni][j] = 0.f;
    const uint32_t vl = sbV + ((lane & 15) * 72 + (lane >> 4) * 8) * 2;
#pragma unroll
    for (int ks = 0; ks < 4; ks++) {
#pragma unroll
        for (int nd = 0; nd < 4; nd++) {
            uint32_t t4[4];
            ldsm4t(t4, vl + ks * 2304 + nd * 32);
#pragma unroll
            for (int mi = 0; mi < 4; mi++) {
                mma16(o[mi][2 * nd], pa[mi][ks], t4);
                mma16(o[mi][2 * nd + 1], pa[mi][ks], t4 + 2);
            }
        }
    }

    __half* ob = g_o + (size_t)win * 64 * INNERD + hd * 64;
#pragma unroll
    for (int mi = 0; mi < 4; mi++) {
        int r = mi * 16 + (lane >> 2);
#pragma unroll
        for (int ni = 0; ni < 8; ni++) {
            int col = ni * 8 + (lane & 3) * 2;
            *(__half2*)&ob[(size_t)r * INNERD + col] =
                __floats2half2_rn(o[mi][ni][0] * inv0[mi], o[mi][ni][1] * inv0[mi]);
            *(__half2*)&ob[(size_t)(r + 8) * INNERD + col] =
                __floats2half2_rn(o[mi][ni][2] * inv1[mi], o[mi][ni][3] * inv1[mi]);
        }
    }
}

extern "C" void kernel_launch(void* const* d_in, const int* in_sizes, int n_in,
                              void* d_out, int out_size) {
    const float* x     = (const float*)d_in[0];
    const float* w_qkv = (const float*)d_in[1];
    const float* w_out = (const float*)d_in[2];
    const float* b_out = (const float*)d_in[3];
    float* out = (float*)d_out;

    cudaFuncSetAttribute(gemm_fp16_k<TOKD, QKVD, 0>,
                         cudaFuncAttributeMaxDynamicSharedMemorySize, GEMM_SMEM);
    cudaFuncSetAttribute(gemm_fp16_k<INNERD, TOKD, 1>,
                         cudaFuncAttributeMaxDynamicSharedMemorySize, GEMM_SMEM);

    perm_wqkv_k<<<dim3(TOKD / 64, QKVD / 32), dim3(32, 8)>>>(w_qkv);
    perm_wout_k<<<dim3(INNERD / 64, TOKD / 32), dim3(32, 8)>>>(w_out, b_out);
    gather_k<<<2048, 256>>>(x);
    gemm_fp16_k<TOKD, QKVD, 0>
        <<<dim3(QKVD / 128, NTOK / 128), 128, GEMM_SMEM>>>(nullptr);
    attn_k<<<dim3(8, 512), 32>>>();
    gemm_fp16_k<INNERD, TOKD, 1>
        <<<dim3(TOKD / 128, NTOK / 128), 128, GEMM_SMEM>>>(out);
}

// round 15
// speedup vs baseline: 1.1847x; 1.0275x over previous
#include <cuda_runtime.h>
#include <cuda_fp16.h>
#include <cstdint>
#include <cstddef>

#define DEV_INLINE __device__ __forceinline__

// B=8, C=64, S=256, WS=32, P=4, HEADS=8, DH=64
constexpr int NTOK = 32768;
constexpr int TOKD = 1024;
constexpr int QKVD = 1536;
constexpr int INNERD = 512;

// ---- static scratch ----
__device__ __half g_tokens[(size_t)NTOK * TOKD];            // [token][k]
__device__ __half g_qkv[(size_t)NTOK * QKVD];               // [token][f]
__device__ __half g_o[(size_t)NTOK * INNERD];               // [token][e]
__device__ uint32_t g_wqkv[(size_t)QKVD * (TOKD / 2)];      // [f][k2]  half2-packed
__device__ uint32_t g_wout[(size_t)TOKD * (INNERD / 2)];    // [dp][e2] half2-packed
__device__ float g_bias[TOKD];

DEV_INLINE void mma16(float* d, const uint32_t* a, const uint32_t* b) {
    asm volatile("mma.sync.aligned.m16n8k16.row.col.f32.f16.f16.f32 "
        "{%0,%1,%2,%3}, {%4,%5,%6,%7}, {%8,%9}, {%0,%1,%2,%3};"
        : "+f"(d[0]), "+f"(d[1]), "+f"(d[2]), "+f"(d[3])
        : "r"(a[0]), "r"(a[1]), "r"(a[2]), "r"(a[3]), "r"(b[0]), "r"(b[1]));
}
DEV_INLINE void cp16(const void* dst, const void* src) {
    uint32_t a = (uint32_t)__cvta_generic_to_shared(dst);
    asm volatile("cp.async.cg.shared.global [%0], [%1], 16;" :: "r"(a), "l"(src));
}
DEV_INLINE void ldsm4(uint32_t* r, uint32_t addr) {
    asm volatile("ldmatrix.sync.aligned.m8n8.x4.shared.b16 {%0,%1,%2,%3}, [%4];"
        : "=r"(r[0]), "=r"(r[1]), "=r"(r[2]), "=r"(r[3]) : "r"(addr));
}
DEV_INLINE void ldsm4t(uint32_t* r, uint32_t addr) {
    asm volatile("ldmatrix.sync.aligned.m8n8.x4.trans.shared.b16 {%0,%1,%2,%3}, [%4];"
        : "=r"(r[0]), "=r"(r[1]), "=r"(r[2]), "=r"(r[3]) : "r"(addr));
}
DEV_INLINE uint32_t h2u(__half2 h) { return *(uint32_t*)&h; }

// ---- weight prep: d' = c*16 + p1*4 + p2 ; src d = (p1*4+p2)*64 + c ----
__global__ void perm_wqkv_k(const float* __restrict__ w) {
    __shared__ uint32_t sm[32][33];
    int k20 = blockIdx.x * 32, f0 = blockIdx.y * 32;
    int tx = threadIdx.x, ty = threadIdx.y;     // (32, 8)
#pragma unroll
    for (int i = 0; i < 4; i++) {
        int k2l = ty + i * 8;
        int d0 = 2 * (k20 + k2l), d1 = d0 + 1;
        int s0 = (d0 & 15) * 64 + (d0 >> 4);
        int s1 = (d1 & 15) * 64 + (d1 >> 4);
        sm[k2l][tx] = h2u(__floats2half2_rn(w[(size_t)s0 * QKVD + f0 + tx],
                                            w[(size_t)s1 * QKVD + f0 + tx]));
    }
    __syncthreads();
#pragma unroll
    for (int i = 0; i < 4; i++) {
        int fl = ty + i * 8;
        g_wqkv[(size_t)(f0 + fl) * (TOKD / 2) + k20 + tx] = sm[tx][fl];
    }
}
__global__ void perm_wout_k(const float* __restrict__ w, const float* __restrict__ b) {
    __shared__ uint32_t sm[32][33];
    int e20 = blockIdx.x * 32, d0 = blockIdx.y * 32;
    int tx = threadIdx.x, ty = threadIdx.y;     // (32, 8)
#pragma unroll
    for (int i = 0; i < 4; i++) {
        int e2l = ty + i * 8;
        int e = 2 * (e20 + e2l);
        sm[e2l][tx] = h2u(__floats2half2_rn(w[(size_t)e * TOKD + d0 + tx],
                                            w[(size_t)(e + 1) * TOKD + d0 + tx]));
    }
    __syncthreads();
#pragma unroll
    for (int i = 0; i < 4; i++) {
        int dl = ty + i * 8;
        int d = d0 + dl;
        int dp = (d & 63) * 16 + (d >> 6);
        g_wout[(size_t)dp * (INNERD / 2) + e20 + tx] = sm[tx][dl];
    }
    if (blockIdx.x == 0 && ty == 0) {
        int d = d0 + tx;
        g_bias[(d & 63) * 16 + (d >> 6)] = b[d];
    }
}

// ---- gather v2: smem-staged, fully coalesced read AND write ----
// block = ((b*8 + h1)*8 + w1)*4 + cg ; handles window (h1,w1), channels cg*16..+15
__global__ void __launch_bounds__(256) gather_k(const float* __restrict__ x) {
    __shared__ __half sm[64 * 264];       // [token][264], pad 8 halfs
    int blk = blockIdx.x;
    int cg = blk & 3;
    int w1 = (blk >> 2) & 7;
    int h1 = (blk >> 5) & 7;
    int b  = blk >> 8;
    int tid = threadIdx.x;
    int warp = tid >> 5, lane = tid & 31;
    int l3 = lane >> 3, f = lane & 7;     // row-in-group, float4 idx (= nw_j)
#pragma unroll
    for (int it = 0; it < 16; it++) {
        int R = warp * 64 + it * 4 + l3;  // 0..511 = cl*32 + hh
        int cl = R >> 5, hh = R & 31;
        int c = cg * 16 + cl;
        size_t xoff = (((size_t)(b * 64 + c) << 8) + h1 * 32 + hh) * 256
                    + w1 * 32 + f * 4;
        float4 v = *(const float4*)&x[xoff];
        uint2 o;
        o.x = h2u(__floats2half2_rn(v.x, v.y));
        o.y = h2u(__floats2half2_rn(v.z, v.w));
        int t = (hh >> 2) * 8 + f;
        *(uint2*)&sm[t * 264 + cl * 16 + (hh & 3) * 4] = o;
    }
    __syncthreads();
    size_t base = (size_t)(((b * 8 + h1) * 8 + w1) * 64) * TOKD + cg * 256;
    int rw = tid >> 5, ch = tid & 31;
#pragma unroll
    for (int p = 0; p < 8; p++) {
        int t = p * 8 + rw;
        *(uint4*)&g_tokens[base + (size_t)t * TOKD + ch * 8] =
            *(const uint4*)&sm[t * 264 + ch * 8];
    }
}

// ---- fp16 GEMM: 128x128 CTA, 2x2 warps of 64x64, K-step 64, double-buffered ----
constexpr int GEMM_SMEM = 73728;
template<int K, int N, int MODE>
__global__ void __launch_bounds__(128, 2) gemm_fp16_k(float* __restrict__ outp) {
    extern __shared__ char smem_raw[];
    __half* Asm = (__half*)smem_raw;
    uint32_t* Bsm = (uint32_t*)(smem_raw + 36864);
    const uint32_t sb = (uint32_t)__cvta_generic_to_shared(smem_raw);

    const __half* A = (MODE == 0) ? g_tokens : g_o;
    const uint32_t* Bp = (MODE == 0) ? g_wqkv : g_wout;
    constexpr int K2 = K / 2;

    const int tid = threadIdx.x, warp = tid >> 5, lane = tid & 31;
    const int wm = warp >> 1, wn = warp & 1;
    const int tm = blockIdx.y * 128, tn = blockIdx.x * 128;
    const int r0 = lane >> 2;

    float acc[4][8][4];
#pragma unroll
    for (int mi = 0; mi < 4; mi++)
#pragma unroll
        for (int ni = 0; ni < 8; ni++)
#pragma unroll
            for (int j = 0; j < 4; j++) acc[mi][ni][j] = 0.f;

    constexpr int KT = K / 64;
    const int lr = tid >> 3, lc = tid & 7;   // load row/chunk

    auto load_stage = [&](int kt, int bf) {
        const int k0 = kt * 64, k20 = kt * 32;
#pragma unroll
        for (int i = 0; i < 8; i++) {
            int r = lr + i * 16;
            cp16(&Asm[bf * 9216 + r * 72 + lc * 8], &A[(size_t)(tm + r) * K + k0 + lc * 8]);
        }
#pragma unroll
        for (int i = 0; i < 8; i++) {
            int r = lr + i * 16;
            cp16(&Bsm[bf * 4608 + r * 36 + lc * 4], &Bp[(size_t)(tn + r) * K2 + k20 + lc * 4]);
        }
        asm volatile("cp.async.commit_group;");
    };

    load_stage(0, 0);

    const uint32_t a_lane = ((wm * 64 + (lane & 15)) * 72 + (lane >> 4) * 8) * 2;
    const uint32_t b_lane = ((wn * 64 + (lane >> 4) * 8 + (lane & 7)) * 36
                             + ((lane >> 3) & 1) * 4) * 4;

    for (int kt = 0; kt < KT; kt++) {
        if (kt + 1 < KT) {
            load_stage(kt + 1, (kt + 1) & 1);
            asm volatile("cp.async.wait_group 1;");
        } else {
            asm volatile("cp.async.wait_group 0;");
        }
        __syncthreads();
        const uint32_t abuf = sb + (kt & 1) * 18432 + a_lane;
        const uint32_t bbuf = sb + 36864 + (kt & 1) * 18432 + b_lane;
#pragma unroll
        for (int ks = 0; ks < 4; ks++) {
            uint32_t a[4][4], bq[8][2];
#pragma unroll
            for (int mi = 0; mi < 4; mi++)
                ldsm4(a[mi], abuf + mi * 2304 + ks * 32);
#pragma unroll
            for (int p = 0; p < 4; p++) {
                uint32_t t4[4];
                ldsm4(t4, bbuf + p * 2304 + ks * 32);
                bq[2 * p][0] = t4[0]; bq[2 * p][1] = t4[1];
                bq[2 * p + 1][0] = t4[2]; bq[2 * p + 1][1] = t4[3];
            }
#pragma unroll
            for (int mi = 0; mi < 4; mi++)
#pragma unroll
                for (int ni = 0; ni < 8; ni++)
                    mma16(acc[mi][ni], a[mi], bq[ni]);
        }
        __syncthreads();
    }
    const int c2 = (lane & 3) * 2;
#pragma unroll
    for (int mi = 0; mi < 4; mi++) {
#pragma unroll
        for (int ni = 0; ni < 8; ni++) {
            int row = tm + wm * 64 + mi * 16 + r0;
            int col = tn + wn * 64 + ni * 8 + c2;
            if (MODE == 0) {
                *(uint32_t*)&g_qkv[(size_t)row * N + col] =
                    h2u(__floats2half2_rn(acc[mi][ni][0], acc[mi][ni][1]));
                *(uint32_t*)&g_qkv[(size_t)(row + 8) * N + col] =
                    h2u(__floats2half2_rn(acc[mi][ni][2], acc[mi][ni][3]));
            } else {
                int win = row >> 6, t = row & 63;
                int b = win >> 6, rem = win & 63;
                size_t cterm = (size_t)(col >> 4) << 16;
                float b0 = g_bias[col], b1 = g_bias[col + 1];
                size_t xr = ((size_t)(b * 64) << 16)
                          + ((size_t)(((rem >> 3) << 5) | ((t >> 3) << 2) | ((col >> 2) & 3)) << 8)
                          + (size_t)(((rem & 7) << 5) | ((t & 7) << 2) | (col & 3));
                *(float2*)&outp[xr + cterm] =
                    make_float2(acc[mi][ni][0] + b0, acc[mi][ni][1] + b1);
                int t8 = t + 8;
                size_t xr8 = ((size_t)(b * 64) << 16)
                           + ((size_t)(((rem >> 3) << 5) | ((t8 >> 3) << 2) | ((col >> 2) & 3)) << 8)
                           + (size_t)(((rem & 7) << 5) | ((t8 & 7) << 2) | (col & 3));
                *(float2*)&outp[xr8 + cterm] =
                    make_float2(acc[mi][ni][2] + b0, acc[mi][ni][3] + b1);
            }
        }
    }
}

// ---- attention: CTA = (window, head), 1 warp, tensor-core S and PV ----
__global__ void __launch_bounds__(32) attn_k() {
    __shared__ __half Qs[64 * 72];       // 9216 B, rows stride 144 B
    __shared__ uint32_t Ksm[64 * 36];    // 9216 B, k2-packed, stride 144 B
    __shared__ __half Vs[64 * 72];       // 9216 B
    const int win = blockIdx.y, hd = blockIdx.x, lane = threadIdx.x;
    const __half* base = g_qkv + (size_t)win * 64 * QKVD + hd * 64;
    const __half2 sc = __floats2half2_rn(0.125f, 0.125f);

#pragma unroll
    for (int i = 0; i < 16; i++) {
        int idx = i * 32 + lane;
        int r = idx >> 3, c8 = idx & 7;
        const __half* rp = base + (size_t)r * QKVD;
        uint4 q4 = *(const uint4*)(rp + c8 * 8);
        __half2* qh = (__half2*)&q4;
        qh[0] = __hmul2(qh[0], sc); qh[1] = __hmul2(qh[1], sc);
        qh[2] = __hmul2(qh[2], sc); qh[3] = __hmul2(qh[3], sc);
        *(uint4*)&Qs[r * 72 + c8 * 8] = q4;
        *(uint4*)&Ksm[r * 36 + c8 * 4] = *(const uint4*)(rp + INNERD + c8 * 8);
        *(uint4*)&Vs[r * 72 + c8 * 8] = *(const uint4*)(rp + 2 * INNERD + c8 * 8);
    }
    __syncwarp();

    const uint32_t sbQ = (uint32_t)__cvta_generic_to_shared(Qs);
    const uint32_t sbK = (uint32_t)__cvta_generic_to_shared(Ksm);
    const uint32_t sbV = (uint32_t)__cvta_generic_to_shared(Vs);

    uint32_t a[4][4][4];
#pragma unroll
    for (int mi = 0; mi < 4; mi++)
#pragma unroll
        for (int ks = 0; ks < 4; ks++)
            ldsm4(a[mi][ks],
                  sbQ + ((mi * 16 + (lane & 15)) * 72 + ks * 16 + (lane >> 4) * 8) * 2);

    float s[4][8][4];
#pragma unroll
    for (int mi = 0; mi < 4; mi++)
#pragma unroll
        for (int ni = 0; ni < 8; ni++)
#pragma unroll
            for (int j = 0; j < 4; j++) s[mi][ni][j] = 0.f;
    const uint32_t kl = sbK + ((lane >> 4) * 8 + (lane & 7)) * 144 + ((lane >> 3) & 1) * 16;
#pragma unroll
    for (int ks = 0; ks < 4; ks++) {
#pragma unroll
        for (int p = 0; p < 4; p++) {
            uint32_t t4[4];
            ldsm4(t4, kl + p * 2304 + ks * 32);
#pragma unroll
            for (int mi = 0; mi < 4; mi++) {
                mma16(s[mi][2 * p], a[mi][ks], t4);
                mma16(s[mi][2 * p + 1], a[mi][ks], t4 + 2);
            }
        }
    }

    float inv0[4], inv1[4];
#pragma unroll
    for (int mi = 0; mi < 4; mi++) {
        float m0 = -1e30f, m1 = -1e30f;
#pragma unroll
        for (int ni = 0; ni < 8; ni++) {
            m0 = fmaxf(m0, fmaxf(s[mi][ni][0], s[mi][ni][1]));
            m1 = fmaxf(m1, fmaxf(s[mi][ni][2], s[mi][ni][3]));
        }
        m0 = fmaxf(m0, __shfl_xor_sync(0xffffffff, m0, 1));
        m0 = fmaxf(m0, __shfl_xor_sync(0xffffffff, m0, 2));
        m1 = fmaxf(m1, __shfl_xor_sync(0xffffffff, m1, 1));
        m1 = fmaxf(m1, __shfl_xor_sync(0xffffffff, m1, 2));
        float s0 = 0.f, s1 = 0.f;
#pragma unroll
        for (int ni = 0; ni < 8; ni++) {
            s[mi][ni][0] = __expf(s[mi][ni][0] - m0);
            s[mi][ni][1] = __expf(s[mi][ni][1] - m0);
            s[mi][ni][2] = __expf(s[mi][ni][2] - m1);
            s[mi][ni][3] = __expf(s[mi][ni][3] - m1);
            s0 += s[mi][ni][0] + s[mi][ni][1];
            s1 += s[mi][ni][2] + s[mi][ni][3];
        }
        s0 += __shfl_xor_sync(0xffffffff, s0, 1);
        s0 += __shfl_xor_sync(0xffffffff, s0, 2);
        s1 += __shfl_xor_sync(0xffffffff, s1, 1);
        s1 += __shfl_xor_sync(0xffffffff, s1, 2);
        inv0[mi] = 1.f / s0; inv1[mi] = 1.f / s1;
    }

    uint32_t pa[4][4][4];
#pragma unroll
    for (int mi = 0; mi < 4; mi++)
#pragma unroll
        for (int ks = 0; ks < 4; ks++) {
            pa[mi][ks][0] = h2u(__floats2half2_rn(s[mi][2 * ks][0], s[mi][2 * ks][1]));
            pa[mi][ks][1] = h2u(__floats2half2_rn(s[mi][2 * ks][2], s[mi][2 * ks][3]));
            pa[mi][ks][2] = h2u(__floats2half2_rn(s[mi][2 * ks + 1][0], s[mi][2 * ks + 1][1]));
            pa[mi][ks][3] = h2u(__floats2half2_rn(s[mi][2 * ks + 1][2], s[mi][2 * ks + 1][3]));
        }

    float o[4][8][4];
#pragma unroll
    for (int mi = 0; mi < 4; mi++)
#pragma unroll
        for (int ni = 0; ni < 8; ni++)
#pragma unroll
            for (int j = 0; j < 4; j++) o[mi][ni][j] = 0.f;
    const uint32_t vl = sbV + ((lane & 15) * 72 + (lane >> 4) * 8) * 2;
#pragma unroll
    for (int ks = 0; ks < 4; ks++) {
#pragma unroll
        for (int nd = 0; nd < 4; nd++) {
            uint32_t t4[4];
            ldsm4t(t4, vl + ks * 2304 + nd * 32);
#pragma unroll
            for (int mi = 0; mi < 4; mi++) {
                mma16(o[mi][2 * nd], pa[mi][ks], t4);
                mma16(o[mi][2 * nd + 1], pa[mi][ks], t4 + 2);
            }
        }
    }

    __half* ob = g_o + (size_t)win * 64 * INNERD + hd * 64;
#pragma unroll
    for (int mi = 0; mi < 4; mi++) {
        int r = mi * 16 + (lane >> 2);
#pragma unroll
        for (int ni = 0; ni < 8; ni++) {
            int col = ni * 8 + (lane & 3) * 2;
            *(__half2*)&ob[(size_t)r * INNERD + col] =
                __floats2half2_rn(o[mi][ni][0] * inv0[mi], o[mi][ni][1] * inv0[mi]);
            *(__half2*)&ob[(size_t)(r + 8) * INNERD + col] =
                __floats2half2_rn(o[mi][ni][2] * inv1[mi], o[mi][ni][3] * inv1[mi]);
        }
    }
}

extern "C" void kernel_launch(void* const* d_in, const int* in_sizes, int n_in,
                              void* d_out, int out_size) {
    const float* x     = (const float*)d_in[0];
    const float* w_qkv = (const float*)d_in[1];
    const float* w_out = (const float*)d_in[2];
    const float* b_out = (const float*)d_in[3];
    float* out = (float*)d_out;

    cudaFuncSetAttribute(gemm_fp16_k<TOKD, QKVD, 0>,
                         cudaFuncAttributeMaxDynamicSharedMemorySize, GEMM_SMEM);
    cudaFuncSetAttribute(gemm_fp16_k<INNERD, TOKD, 1>,
                         cudaFuncAttributeMaxDynamicSharedMemorySize, GEMM_SMEM);

    perm_wqkv_k<<<dim3(TOKD / 64, QKVD / 32), dim3(32, 8)>>>(w_qkv);
    perm_wout_k<<<dim3(INNERD / 64, TOKD / 32), dim3(32, 8)>>>(w_out, b_out);
    gather_k<<<2048, 256>>>(x);
    gemm_fp16_k<TOKD, QKVD, 0>
        <<<dim3(QKVD / 128, NTOK / 128), 128, GEMM_SMEM>>>(nullptr);
    attn_k<<<dim3(8, 512), 32>>>();
    gemm_fp16_k<INNERD, TOKD, 1>
        <<<dim3(TOKD / 128, NTOK / 128), 128, GEMM_SMEM>>>(out);
}

// round 16
// speedup vs baseline: 1.2554x; 1.0597x over previous
#include <cuda_runtime.h>
#include <cuda_fp16.h>
#include <cstdint>
#include <cstddef>

#define DEV_INLINE __device__ __forceinline__

// B=8, C=64, S=256, WS=32, P=4, HEADS=8, DH=64
constexpr int NTOK = 32768;
constexpr int TOKD = 1024;
constexpr int QKVD = 1536;
constexpr int INNERD = 512;

// ---- static scratch ----
__device__ __half g_tokens[(size_t)NTOK * TOKD];            // [token][k]
__device__ __half g_qkv[(size_t)NTOK * QKVD];               // [token][f]
__device__ __half g_o[(size_t)NTOK * INNERD];               // [token][e]
__device__ uint32_t g_wqkv[(size_t)QKVD * (TOKD / 2)];      // [f][k2]  half2-packed
__device__ uint32_t g_wout[(size_t)TOKD * (INNERD / 2)];    // [dp][e2] half2-packed
__device__ float g_bias[TOKD];

DEV_INLINE void mma16(float* d, const uint32_t* a, const uint32_t* b) {
    asm volatile("mma.sync.aligned.m16n8k16.row.col.f32.f16.f16.f32 "
        "{%0,%1,%2,%3}, {%4,%5,%6,%7}, {%8,%9}, {%0,%1,%2,%3};"
        : "+f"(d[0]), "+f"(d[1]), "+f"(d[2]), "+f"(d[3])
        : "r"(a[0]), "r"(a[1]), "r"(a[2]), "r"(a[3]), "r"(b[0]), "r"(b[1]));
}
DEV_INLINE void cp16(const void* dst, const void* src) {
    uint32_t a = (uint32_t)__cvta_generic_to_shared(dst);
    asm volatile("cp.async.ca.shared.global [%0], [%1], 16;" :: "r"(a), "l"(src));
}
DEV_INLINE void ldsm4(uint32_t* r, uint32_t addr) {
    asm volatile("ldmatrix.sync.aligned.m8n8.x4.shared.b16 {%0,%1,%2,%3}, [%4];"
        : "=r"(r[0]), "=r"(r[1]), "=r"(r[2]), "=r"(r[3]) : "r"(addr));
}
DEV_INLINE void ldsm4t(uint32_t* r, uint32_t addr) {
    asm volatile("ldmatrix.sync.aligned.m8n8.x4.trans.shared.b16 {%0,%1,%2,%3}, [%4];"
        : "=r"(r[0]), "=r"(r[1]), "=r"(r[2]), "=r"(r[3]) : "r"(addr));
}
DEV_INLINE uint32_t h2u(__half2 h) { return *(uint32_t*)&h; }

// ---- weight prep: d' = c*16 + p1*4 + p2 ; src d = (p1*4+p2)*64 + c ----
__global__ void perm_wqkv_k(const float* __restrict__ w) {
    __shared__ uint32_t sm[32][33];
    int k20 = blockIdx.x * 32, f0 = blockIdx.y * 32;
    int tx = threadIdx.x, ty = threadIdx.y;     // (32, 8)
#pragma unroll
    for (int i = 0; i < 4; i++) {
        int k2l = ty + i * 8;
        int d0 = 2 * (k20 + k2l), d1 = d0 + 1;
        int s0 = (d0 & 15) * 64 + (d0 >> 4);
        int s1 = (d1 & 15) * 64 + (d1 >> 4);
        sm[k2l][tx] = h2u(__floats2half2_rn(w[(size_t)s0 * QKVD + f0 + tx],
                                            w[(size_t)s1 * QKVD + f0 + tx]));
    }
    __syncthreads();
#pragma unroll
    for (int i = 0; i < 4; i++) {
        int fl = ty + i * 8;
        g_wqkv[(size_t)(f0 + fl) * (TOKD / 2) + k20 + tx] = sm[tx][fl];
    }
}
__global__ void perm_wout_k(const float* __restrict__ w, const float* __restrict__ b) {
    __shared__ uint32_t sm[32][33];
    int e20 = blockIdx.x * 32, d0 = blockIdx.y * 32;
    int tx = threadIdx.x, ty = threadIdx.y;     // (32, 8)
#pragma unroll
    for (int i = 0; i < 4; i++) {
        int e2l = ty + i * 8;
        int e = 2 * (e20 + e2l);
        sm[e2l][tx] = h2u(__floats2half2_rn(w[(size_t)e * TOKD + d0 + tx],
                                            w[(size_t)(e + 1) * TOKD + d0 + tx]));
    }
    __syncthreads();
#pragma unroll
    for (int i = 0; i < 4; i++) {
        int dl = ty + i * 8;
        int d = d0 + dl;
        int dp = (d & 63) * 16 + (d >> 6);
        g_wout[(size_t)dp * (INNERD / 2) + e20 + tx] = sm[tx][dl];
    }
    if (blockIdx.x == 0 && ty == 0) {
        int d = d0 + tx;
        g_bias[(d & 63) * 16 + (d >> 6)] = b[d];
    }
}

// ---- gather v2: smem-staged, fully coalesced read AND write ----
// block = ((b*8 + h1)*8 + w1)*4 + cg ; handles window (h1,w1), channels cg*16..+15
__global__ void __launch_bounds__(256) gather_k(const float* __restrict__ x) {
    __shared__ __half sm[64 * 264];       // [token][264], pad 8 halfs
    int blk = blockIdx.x;
    int cg = blk & 3;
    int w1 = (blk >> 2) & 7;
    int h1 = (blk >> 5) & 7;
    int b  = blk >> 8;
    int tid = threadIdx.x;
    int warp = tid >> 5, lane = tid & 31;
    int l3 = lane >> 3, f = lane & 7;     // row-in-group, float4 idx (= nw_j)
#pragma unroll
    for (int it = 0; it < 16; it++) {
        int R = warp * 64 + it * 4 + l3;  // 0..511 = cl*32 + hh
        int cl = R >> 5, hh = R & 31;
        int c = cg * 16 + cl;
        size_t xoff = (((size_t)(b * 64 + c) << 8) + h1 * 32 + hh) * 256
                    + w1 * 32 + f * 4;
        float4 v = *(const float4*)&x[xoff];
        uint2 o;
        o.x = h2u(__floats2half2_rn(v.x, v.y));
        o.y = h2u(__floats2half2_rn(v.z, v.w));
        int t = (hh >> 2) * 8 + f;
        *(uint2*)&sm[t * 264 + cl * 16 + (hh & 3) * 4] = o;
    }
    __syncthreads();
    size_t base = (size_t)(((b * 8 + h1) * 8 + w1) * 64) * TOKD + cg * 256;
    int rw = tid >> 5, ch = tid & 31;
#pragma unroll
    for (int p = 0; p < 8; p++) {
        int t = p * 8 + rw;
        *(uint4*)&g_tokens[base + (size_t)t * TOKD + ch * 8] =
            *(const uint4*)&sm[t * 264 + ch * 8];
    }
}

// ---- fp16 GEMM: 128x128 CTA, 2x2 warps of 64x64, K-step 64, double-buffered ----
constexpr int GEMM_SMEM = 73728;
template<int K, int N, int MODE>
__global__ void __launch_bounds__(128, 2) gemm_fp16_k(float* __restrict__ outp) {
    extern __shared__ char smem_raw[];
    __half* Asm = (__half*)smem_raw;
    uint32_t* Bsm = (uint32_t*)(smem_raw + 36864);
    const uint32_t sb = (uint32_t)__cvta_generic_to_shared(smem_raw);

    const __half* A = (MODE == 0) ? g_tokens : g_o;
    const uint32_t* Bp = (MODE == 0) ? g_wqkv : g_wout;
    constexpr int K2 = K / 2;

    const int tid = threadIdx.x, warp = tid >> 5, lane = tid & 31;
    const int wm = warp >> 1, wn = warp & 1;
    const int tm = blockIdx.y * 128, tn = blockIdx.x * 128;
    const int r0 = lane >> 2;

    float acc[4][8][4];
#pragma unroll
    for (int mi = 0; mi < 4; mi++)
#pragma unroll
        for (int ni = 0; ni < 8; ni++)
#pragma unroll
            for (int j = 0; j < 4; j++) acc[mi][ni][j] = 0.f;

    constexpr int KT = K / 64;
    const int lr = tid >> 3, lc = tid & 7;   // load row/chunk

    auto load_stage = [&](int kt, int bf) {
        const int k0 = kt * 64, k20 = kt * 32;
#pragma unroll
        for (int i = 0; i < 8; i++) {
            int r = lr + i * 16;
            cp16(&Asm[bf * 9216 + r * 72 + lc * 8], &A[(size_t)(tm + r) * K + k0 + lc * 8]);
        }
#pragma unroll
        for (int i = 0; i < 8; i++) {
            int r = lr + i * 16;
            cp16(&Bsm[bf * 4608 + r * 36 + lc * 4], &Bp[(size_t)(tn + r) * K2 + k20 + lc * 4]);
        }
        asm volatile("cp.async.commit_group;");
    };

    load_stage(0, 0);

    const uint32_t a_lane = ((wm * 64 + (lane & 15)) * 72 + (lane >> 4) * 8) * 2;
    const uint32_t b_lane = ((wn * 64 + (lane >> 4) * 8 + (lane & 7)) * 36
                             + ((lane >> 3) & 1) * 4) * 4;

    for (int kt = 0; kt < KT; kt++) {
        if (kt + 1 < KT) {
            load_stage(kt + 1, (kt + 1) & 1);
            asm volatile("cp.async.wait_group 1;");
        } else {
            asm volatile("cp.async.wait_group 0;");
        }
        __syncthreads();
        const uint32_t abuf = sb + (kt & 1) * 18432 + a_lane;
        const uint32_t bbuf = sb + 36864 + (kt & 1) * 18432 + b_lane;
#pragma unroll
        for (int ks = 0; ks < 4; ks++) {
            uint32_t a[4][4], bq[8][2];
#pragma unroll
            for (int mi = 0; mi < 4; mi++)
                ldsm4(a[mi], abuf + mi * 2304 + ks * 32);
#pragma unroll
            for (int p = 0; p < 4; p++) {
                uint32_t t4[4];
                ldsm4(t4, bbuf + p * 2304 + ks * 32);
                bq[2 * p][0] = t4[0]; bq[2 * p][1] = t4[1];
                bq[2 * p + 1][0] = t4[2]; bq[2 * p + 1][1] = t4[3];
            }
#pragma unroll
            for (int mi = 0; mi < 4; mi++)
#pragma unroll
                for (int ni = 0; ni < 8; ni++)
                    mma16(acc[mi][ni], a[mi], bq[ni]);
        }
        __syncthreads();
    }
    const int c2 = (lane & 3) * 2;
#pragma unroll
    for (int mi = 0; mi < 4; mi++) {
#pragma unroll
        for (int ni = 0; ni < 8; ni++) {
            int row = tm + wm * 64 + mi * 16 + r0;
            int col = tn + wn * 64 + ni * 8 + c2;
            if (MODE == 0) {
                *(uint32_t*)&g_qkv[(size_t)row * N + col] =
                    h2u(__floats2half2_rn(acc[mi][ni][0], acc[mi][ni][1]));
                *(uint32_t*)&g_qkv[(size_t)(row + 8) * N + col] =
                    h2u(__floats2half2_rn(acc[mi][ni][2], acc[mi][ni][3]));
            } else {
                int win = row >> 6, t = row & 63;
                int b = win >> 6, rem = win & 63;
                size_t cterm = (size_t)(col >> 4) << 16;
                float b0 = g_bias[col], b1 = g_bias[col + 1];
                size_t xr = ((size_t)(b * 64) << 16)
                          + ((size_t)(((rem >> 3) << 5) | ((t >> 3) << 2) | ((col >> 2) & 3)) << 8)
                          + (size_t)(((rem & 7) << 5) | ((t & 7) << 2) | (col & 3));
                *(float2*)&outp[xr + cterm] =
                    make_float2(acc[mi][ni][0] + b0, acc[mi][ni][1] + b1);
                int t8 = t + 8;
                size_t xr8 = ((size_t)(b * 64) << 16)
                           + ((size_t)(((rem >> 3) << 5) | ((t8 >> 3) << 2) | ((col >> 2) & 3)) << 8)
                           + (size_t)(((rem & 7) << 5) | ((t8 & 7) << 2) | (col & 3));
                *(float2*)&outp[xr8 + cterm] =
                    make_float2(acc[mi][ni][2] + b0, acc[mi][ni][3] + b1);
            }
        }
    }
}

// ---- attention: CTA = (window, head), 1 warp, tensor-core S and PV ----
__global__ void __launch_bounds__(32) attn_k() {
    __shared__ __half Qs[64 * 72];       // 9216 B, rows stride 144 B
    __shared__ uint32_t Ksm[64 * 36];    // 9216 B, k2-packed, stride 144 B
    __shared__ __half Vs[64 * 72];       // 9216 B
    const int win = blockIdx.y, hd = blockIdx.x, lane = threadIdx.x;
    const __half* base = g_qkv + (size_t)win * 64 * QKVD + hd * 64;
    const __half2 sc = __floats2half2_rn(0.125f, 0.125f);

#pragma unroll
    for (int i = 0; i < 16; i++) {
        int idx = i * 32 + lane;
        int r = idx >> 3, c8 = idx & 7;
        const __half* rp = base + (size_t)r * QKVD;
        uint4 q4 = *(const uint4*)(rp + c8 * 8);
        __half2* qh = (__half2*)&q4;
        qh[0] = __hmul2(qh[0], sc); qh[1] = __hmul2(qh[1], sc);
        qh[2] = __hmul2(qh[2], sc); qh[3] = __hmul2(qh[3], sc);
        *(uint4*)&Qs[r * 72 + c8 * 8] = q4;
        *(uint4*)&Ksm[r * 36 + c8 * 4] = *(const uint4*)(rp + INNERD + c8 * 8);
        *(uint4*)&Vs[r * 72 + c8 * 8] = *(const uint4*)(rp + 2 * INNERD + c8 * 8);
    }
    __syncwarp();

    const uint32_t sbQ = (uint32_t)__cvta_generic_to_shared(Qs);
    const uint32_t sbK = (uint32_t)__cvta_generic_to_shared(Ksm);
    const uint32_t sbV = (uint32_t)__cvta_generic_to_shared(Vs);

    uint32_t a[4][4][4];
#pragma unroll
    for (int mi = 0; mi < 4; mi++)
#pragma unroll
        for (int ks = 0; ks < 4; ks++)
            ldsm4(a[mi][ks],
                  sbQ + ((mi * 16 + (lane & 15)) * 72 + ks * 16 + (lane >> 4) * 8) * 2);

    float s[4][8][4];
#pragma unroll
    for (int mi = 0; mi < 4; mi++)
#pragma unroll
        for (int ni = 0; ni < 8; ni++)
#pragma unroll
            for (int j = 0; j < 4; j++) s[mi][ni][j] = 0.f;
    const uint32_t kl = sbK + ((lane >> 4) * 8 + (lane & 7)) * 144 + ((lane >> 3) & 1) * 16;
#pragma unroll
    for (int ks = 0; ks < 4; ks++) {
#pragma unroll
        for (int p = 0; p < 4; p++) {
            uint32_t t4[4];
            ldsm4(t4, kl + p * 2304 + ks * 32);
#pragma unroll
            for (int mi = 0; mi < 4; mi++) {
                mma16(s[mi][2 * p], a[mi][ks], t4);
                mma16(s[mi][2 * p + 1], a[mi][ks], t4 + 2);
            }
        }
    }

    float inv0[4], inv1[4];
#pragma unroll
    for (int mi = 0; mi < 4; mi++) {
        float m0 = -1e30f, m1 = -1e30f;
#pragma unroll
        for (int ni = 0; ni < 8; ni++) {
            m0 = fmaxf(m0, fmaxf(s[mi][ni][0], s[mi][ni][1]));
            m1 = fmaxf(m1, fmaxf(s[mi][ni][2], s[mi][ni][3]));
        }
        m0 = fmaxf(m0, __shfl_xor_sync(0xffffffff, m0, 1));
        m0 = fmaxf(m0, __shfl_xor_sync(0xffffffff, m0, 2));
        m1 = fmaxf(m1, __shfl_xor_sync(0xffffffff, m1, 1));
        m1 = fmaxf(m1, __shfl_xor_sync(0xffffffff, m1, 2));
        float s0 = 0.f, s1 = 0.f;
#pragma unroll
        for (int ni = 0; ni < 8; ni++) {
            s[mi][ni][0] = __expf(s[mi][ni][0] - m0);
            s[mi][ni][1] = __expf(s[mi][ni][1] - m0);
            s[mi][ni][2] = __expf(s[mi][ni][2] - m1);
            s[mi][ni][3] = __expf(s[mi][ni][3] - m1);
            s0 += s[mi][ni][0] + s[mi][ni][1];
            s1 += s[mi][ni][2] + s[mi][ni][3];
        }
        s0 += __shfl_xor_sync(0xffffffff, s0, 1);
        s0 += __shfl_xor_sync(0xffffffff, s0, 2);
        s1 += __shfl_xor_sync(0xffffffff, s1, 1);
        s1 += __shfl_xor_sync(0xffffffff, s1, 2);
        inv0[mi] = 1.f / s0; inv1[mi] = 1.f / s1;
    }

    uint32_t pa[4][4][4];
#pragma unroll
    for (int mi = 0; mi < 4; mi++)
#pragma unroll
        for (int ks = 0; ks < 4; ks++) {
            pa[mi][ks][0] = h2u(__floats2half2_rn(s[mi][2 * ks][0], s[mi][2 * ks][1]));
            pa[mi][ks][1] = h2u(__floats2half2_rn(s[mi][2 * ks][2], s[mi][2 * ks][3]));
            pa[mi][ks][2] = h2u(__floats2half2_rn(s[mi][2 * ks + 1][0], s[mi][2 * ks + 1][1]));
            pa[mi][ks][3] = h2u(__floats2half2_rn(s[mi][2 * ks + 1][2], s[mi][2 * ks + 1][3]));
        }

    float o[4][8][4];
#pragma unroll
    for (int mi = 0; mi < 4; mi++)
#pragma unroll
        for (int ni = 0; ni < 8; ni++)
#pragma unroll
            for (int j = 0; j < 4; j++) o[mi][ni][j] = 0.f;
    const uint32_t vl = sbV + ((lane & 15) * 72 + (lane >> 4) * 8) * 2;
#pragma unroll
    for (int ks = 0; ks < 4; ks++) {
#pragma unroll
        for (int nd = 0; nd < 4; nd++) {
            uint32_t t4[4];
            ldsm4t(t4, vl + ks * 2304 + nd * 32);
#pragma unroll
            for (int mi = 0; mi < 4; mi++) {
                mma16(o[mi][2 * nd], pa[mi][ks], t4);
                mma16(o[mi][2 * nd + 1], pa[mi][ks], t4 + 2);
            }
        }
    }

    __half* ob = g_o + (size_t)win * 64 * INNERD + hd * 64;
#pragma unroll
    for (int mi = 0; mi < 4; mi++) {
        int r = mi * 16 + (lane >> 2);
#pragma unroll
        for (int ni = 0; ni < 8; ni++) {
            int col = ni * 8 + (lane & 3) * 2;
            *(__half2*)&ob[(size_t)r * INNERD + col] =
                __floats2half2_rn(o[mi][ni][0] * inv0[mi], o[mi][ni][1] * inv0[mi]);
            *(__half2*)&ob[(size_t)(r + 8) * INNERD + col] =
                __floats2half2_rn(o[mi][ni][2] * inv1[mi], o[mi][ni][3] * inv1[mi]);
        }
    }
}

extern "C" void kernel_launch(void* const* d_in, const int* in_sizes, int n_in,
                              void* d_out, int out_size) {
    const float* x     = (const float*)d_in[0];
    const float* w_qkv = (const float*)d_in[1];
    const float* w_out = (const float*)d_in[2];
    const float* b_out = (const float*)d_in[3];
    float* out = (float*)d_out;

    cudaFuncSetAttribute(gemm_fp16_k<TOKD, QKVD, 0>,
                         cudaFuncAttributeMaxDynamicSharedMemorySize, GEMM_SMEM);
    cudaFuncSetAttribute(gemm_fp16_k<INNERD, TOKD, 1>,
                         cudaFuncAttributeMaxDynamicSharedMemorySize, GEMM_SMEM);

    perm_wqkv_k<<<dim3(TOKD / 64, QKVD / 32), dim3(32, 8)>>>(w_qkv);
    perm_wout_k<<<dim3(INNERD / 64, TOKD / 32), dim3(32, 8)>>>(w_out, b_out);
    gather_k<<<2048, 256>>>(x);
    gemm_fp16_k<TOKD, QKVD, 0>
        <<<dim3(QKVD / 128, NTOK / 128), 128, GEMM_SMEM>>>(nullptr);
    attn_k<<<dim3(8, 512), 32>>>();
    gemm_fp16_k<INNERD, TOKD, 1>
        <<<dim3(TOKD / 128, NTOK / 128), 128, GEMM_SMEM>>>(out);
}

// round 17
// speedup vs baseline: 1.2718x; 1.0131x over previous
#include <cuda_runtime.h>
#include <cuda_fp16.h>
#include <cstdint>
#include <cstddef>

#define DEV_INLINE __device__ __forceinline__

// B=8, C=64, S=256, WS=32, P=4, HEADS=8, DH=64
constexpr int NTOK = 32768;
constexpr int TOKD = 1024;
constexpr int QKVD = 1536;
constexpr int INNERD = 512;

// ---- static scratch ----
__device__ __half g_tokens[(size_t)NTOK * TOKD];            // [token][k]
__device__ __half g_qkv[(size_t)NTOK * QKVD];               // [token][f]
__device__ __half g_o[(size_t)NTOK * INNERD];               // [token][e]
__device__ uint32_t g_wqkv[(size_t)QKVD * (TOKD / 2)];      // [f][k2]  half2-packed
__device__ uint32_t g_wout[(size_t)TOKD * (INNERD / 2)];    // [dp][e2] half2-packed
__device__ float g_bias[TOKD];

DEV_INLINE void mma16(float* d, const uint32_t* a, const uint32_t* b) {
    asm volatile("mma.sync.aligned.m16n8k16.row.col.f32.f16.f16.f32 "
        "{%0,%1,%2,%3}, {%4,%5,%6,%7}, {%8,%9}, {%0,%1,%2,%3};"
        : "+f"(d[0]), "+f"(d[1]), "+f"(d[2]), "+f"(d[3])
        : "r"(a[0]), "r"(a[1]), "r"(a[2]), "r"(a[3]), "r"(b[0]), "r"(b[1]));
}
DEV_INLINE void cp16(const void* dst, const void* src) {
    uint32_t a = (uint32_t)__cvta_generic_to_shared(dst);
    asm volatile("cp.async.ca.shared.global [%0], [%1], 16;" :: "r"(a), "l"(src));
}
DEV_INLINE void ldsm4(uint32_t* r, uint32_t addr) {
    asm volatile("ldmatrix.sync.aligned.m8n8.x4.shared.b16 {%0,%1,%2,%3}, [%4];"
        : "=r"(r[0]), "=r"(r[1]), "=r"(r[2]), "=r"(r[3]) : "r"(addr));
}
DEV_INLINE void ldsm4t(uint32_t* r, uint32_t addr) {
    asm volatile("ldmatrix.sync.aligned.m8n8.x4.trans.shared.b16 {%0,%1,%2,%3}, [%4];"
        : "=r"(r[0]), "=r"(r[1]), "=r"(r[2]), "=r"(r[3]) : "r"(addr));
}
DEV_INLINE uint32_t h2u(__half2 h) { return *(uint32_t*)&h; }

// ---- weight prep: d' = c*16 + p1*4 + p2 ; src d = (p1*4+p2)*64 + c ----
__global__ void perm_wqkv_k(const float* __restrict__ w) {
    __shared__ uint32_t sm[32][33];
    int k20 = blockIdx.x * 32, f0 = blockIdx.y * 32;
    int tx = threadIdx.x, ty = threadIdx.y;     // (32, 8)
#pragma unroll
    for (int i = 0; i < 4; i++) {
        int k2l = ty + i * 8;
        int d0 = 2 * (k20 + k2l), d1 = d0 + 1;
        int s0 = (d0 & 15) * 64 + (d0 >> 4);
        int s1 = (d1 & 15) * 64 + (d1 >> 4);
        sm[k2l][tx] = h2u(__floats2half2_rn(w[(size_t)s0 * QKVD + f0 + tx],
                                            w[(size_t)s1 * QKVD + f0 + tx]));
    }
    __syncthreads();
#pragma unroll
    for (int i = 0; i < 4; i++) {
        int fl = ty + i * 8;
        g_wqkv[(size_t)(f0 + fl) * (TOKD / 2) + k20 + tx] = sm[tx][fl];
    }
}
__global__ void perm_wout_k(const float* __restrict__ w, const float* __restrict__ b) {
    __shared__ uint32_t sm[32][33];
    int e20 = blockIdx.x * 32, d0 = blockIdx.y * 32;
    int tx = threadIdx.x, ty = threadIdx.y;     // (32, 8)
#pragma unroll
    for (int i = 0; i < 4; i++) {
        int e2l = ty + i * 8;
        int e = 2 * (e20 + e2l);
        sm[e2l][tx] = h2u(__floats2half2_rn(w[(size_t)e * TOKD + d0 + tx],
                                            w[(size_t)(e + 1) * TOKD + d0 + tx]));
    }
    __syncthreads();
#pragma unroll
    for (int i = 0; i < 4; i++) {
        int dl = ty + i * 8;
        int d = d0 + dl;
        int dp = (d & 63) * 16 + (d >> 6);
        g_wout[(size_t)dp * (INNERD / 2) + e20 + tx] = sm[tx][dl];
    }
    if (blockIdx.x == 0 && ty == 0) {
        int d = d0 + tx;
        g_bias[(d & 63) * 16 + (d >> 6)] = b[d];
    }
}

// ---- gather v2: smem-staged, fully coalesced read AND write ----
__global__ void __launch_bounds__(256) gather_k(const float* __restrict__ x) {
    __shared__ __half sm[64 * 264];       // [token][264], pad 8 halfs
    int blk = blockIdx.x;
    int cg = blk & 3;
    int w1 = (blk >> 2) & 7;
    int h1 = (blk >> 5) & 7;
    int b  = blk >> 8;
    int tid = threadIdx.x;
    int warp = tid >> 5, lane = tid & 31;
    int l3 = lane >> 3, f = lane & 7;
#pragma unroll
    for (int it = 0; it < 16; it++) {
        int R = warp * 64 + it * 4 + l3;  // 0..511 = cl*32 + hh
        int cl = R >> 5, hh = R & 31;
        int c = cg * 16 + cl;
        size_t xoff = (((size_t)(b * 64 + c) << 8) + h1 * 32 + hh) * 256
                    + w1 * 32 + f * 4;
        float4 v = *(const float4*)&x[xoff];
        uint2 o;
        o.x = h2u(__floats2half2_rn(v.x, v.y));
        o.y = h2u(__floats2half2_rn(v.z, v.w));
        int t = (hh >> 2) * 8 + f;
        *(uint2*)&sm[t * 264 + cl * 16 + (hh & 3) * 4] = o;
    }
    __syncthreads();
    size_t base = (size_t)(((b * 8 + h1) * 8 + w1) * 64) * TOKD + cg * 256;
    int rw = tid >> 5, ch = tid & 31;
#pragma unroll
    for (int p = 0; p < 8; p++) {
        int t = p * 8 + rw;
        *(uint4*)&g_tokens[base + (size_t)t * TOKD + ch * 8] =
            *(const uint4*)&sm[t * 264 + ch * 8];
    }
}

// ---- fp16 GEMM: 128x128 CTA, 2x2 warps of 64x64, K-step 64, double-buffered ----
constexpr int GEMM_SMEM = 73728;
template<int K, int N, int MODE>
__global__ void __launch_bounds__(128, 2) gemm_fp16_k(float* __restrict__ outp) {
    extern __shared__ char smem_raw[];
    __half* Asm = (__half*)smem_raw;
    uint32_t* Bsm = (uint32_t*)(smem_raw + 36864);
    const uint32_t sb = (uint32_t)__cvta_generic_to_shared(smem_raw);

    const __half* A = (MODE == 0) ? g_tokens : g_o;
    const uint32_t* Bp = (MODE == 0) ? g_wqkv : g_wout;
    constexpr int K2 = K / 2;

    const int tid = threadIdx.x, warp = tid >> 5, lane = tid & 31;
    const int wm = warp >> 1, wn = warp & 1;
    const int tm = blockIdx.y * 128, tn = blockIdx.x * 128;
    const int r0 = lane >> 2;

    float acc[4][8][4];
#pragma unroll
    for (int mi = 0; mi < 4; mi++)
#pragma unroll
        for (int ni = 0; ni < 8; ni++)
#pragma unroll
            for (int j = 0; j < 4; j++) acc[mi][ni][j] = 0.f;

    constexpr int KT = K / 64;
    const int lr = tid >> 3, lc = tid & 7;

    auto load_stage = [&](int kt, int bf) {
        const int k0 = kt * 64, k20 = kt * 32;
#pragma unroll
        for (int i = 0; i < 8; i++) {
            int r = lr + i * 16;
            cp16(&Asm[bf * 9216 + r * 72 + lc * 8], &A[(size_t)(tm + r) * K + k0 + lc * 8]);
        }
#pragma unroll
        for (int i = 0; i < 8; i++) {
            int r = lr + i * 16;
            cp16(&Bsm[bf * 4608 + r * 36 + lc * 4], &Bp[(size_t)(tn + r) * K2 + k20 + lc * 4]);
        }
        asm volatile("cp.async.commit_group;");
    };

    load_stage(0, 0);

    const uint32_t a_lane = ((wm * 64 + (lane & 15)) * 72 + (lane >> 4) * 8) * 2;
    const uint32_t b_lane = ((wn * 64 + (lane >> 4) * 8 + (lane & 7)) * 36
                             + ((lane >> 3) & 1) * 4) * 4;

    for (int kt = 0; kt < KT; kt++) {
        if (kt + 1 < KT) {
            load_stage(kt + 1, (kt + 1) & 1);
            asm volatile("cp.async.wait_group 1;");
        } else {
            asm volatile("cp.async.wait_group 0;");
        }
        __syncthreads();
        const uint32_t abuf = sb + (kt & 1) * 18432 + a_lane;
        const uint32_t bbuf = sb + 36864 + (kt & 1) * 18432 + b_lane;
#pragma unroll
        for (int ks = 0; ks < 4; ks++) {
            uint32_t a[4][4], bq[8][2];
#pragma unroll
            for (int mi = 0; mi < 4; mi++)
                ldsm4(a[mi], abuf + mi * 2304 + ks * 32);
#pragma unroll
            for (int p = 0; p < 4; p++) {
                uint32_t t4[4];
                ldsm4(t4, bbuf + p * 2304 + ks * 32);
                bq[2 * p][0] = t4[0]; bq[2 * p][1] = t4[1];
                bq[2 * p + 1][0] = t4[2]; bq[2 * p + 1][1] = t4[3];
            }
#pragma unroll
            for (int mi = 0; mi < 4; mi++)
#pragma unroll
                for (int ni = 0; ni < 8; ni++)
                    mma16(acc[mi][ni], a[mi], bq[ni]);
        }
        __syncthreads();
    }
    const int c2 = (lane & 3) * 2;
    if (MODE == 0) {
#pragma unroll
        for (int mi = 0; mi < 4; mi++) {
#pragma unroll
            for (int ni = 0; ni < 8; ni++) {
                int row = tm + wm * 64 + mi * 16 + r0;
                int col = tn + wn * 64 + ni * 8 + c2;
                *(uint32_t*)&g_qkv[(size_t)row * N + col] =
                    h2u(__floats2half2_rn(acc[mi][ni][0], acc[mi][ni][1]));
                *(uint32_t*)&g_qkv[(size_t)(row + 8) * N + col] =
                    h2u(__floats2half2_rn(acc[mi][ni][2], acc[mi][ni][3]));
            }
        }
    } else {
        // staged epilogue: CTA output = 256 rows x 64 contiguous floats in x layout
        float* smf = (float*)smem_raw;   // [256][66] floats = 67584 B
#pragma unroll
        for (int mi = 0; mi < 4; mi++) {
#pragma unroll
            for (int ni = 0; ni < 8; ni++) {
                int tl = mi * 16 + r0;                 // token within window (<56)
                int colL = wn * 64 + ni * 8 + c2;      // local d'
                int col = tn + colL;
                float b0 = g_bias[col], b1 = g_bias[col + 1];
                int R = (colL >> 4) * 32 + (tl >> 3) * 4 + ((colL >> 2) & 3);
                int W = wm * 32 + (tl & 7) * 4 + (colL & 3);
                *(float2*)&smf[R * 66 + W] =
                    make_float2(acc[mi][ni][0] + b0, acc[mi][ni][1] + b1);
                *(float2*)&smf[(R + 4) * 66 + W] =
                    make_float2(acc[mi][ni][2] + b0, acc[mi][ni][3] + b1);
            }
        }
        __syncthreads();
        int win0 = tm >> 6;
        int b = win0 >> 6, rem = win0 & 63;
        int h1 = rem >> 3, w1b = rem & 7;   // w1b even; covers w1b, w1b+1
        int cb = tn >> 4;
#pragma unroll 4
        for (int i = 0; i < 64; i++) {
            int R = i * 4 + warp;
            int c_loc = R >> 5, t3 = (R >> 2) & 7, p1 = R & 3;
            int hh = h1 * 32 + t3 * 4 + p1;
            size_t goff = ((((size_t)(b * 64 + cb + c_loc)) << 8) + hh) * 256
                        + w1b * 32 + lane * 2;
            *(float2*)&outp[goff] = *(const float2*)&smf[R * 66 + lane * 2];
        }
    }
}

// ---- attention: CTA = (window, head), 2 warps (32 query rows each) ----
__global__ void __launch_bounds__(64) attn_k() {
    __shared__ __half Qs[64 * 72];       // rows stride 144 B
    __shared__ uint32_t Ksm[64 * 36];    // k2-packed, stride 144 B
    __shared__ __half Vs[64 * 72];
    const int win = blockIdx.y, hd = blockIdx.x;
    const int tid = threadIdx.x, warp = tid >> 5, lane = tid & 31;
    const __half* base = g_qkv + (size_t)win * 64 * QKVD + hd * 64;
    const __half2 sc = __floats2half2_rn(0.125f, 0.125f);

#pragma unroll
    for (int i = 0; i < 8; i++) {
        int idx = i * 64 + tid;
        int r = idx >> 3, c8 = idx & 7;
        const __half* rp = base + (size_t)r * QKVD;
        uint4 q4 = *(const uint4*)(rp + c8 * 8);
        __half2* qh = (__half2*)&q4;
        qh[0] = __hmul2(qh[0], sc); qh[1] = __hmul2(qh[1], sc);
        qh[2] = __hmul2(qh[2], sc); qh[3] = __hmul2(qh[3], sc);
        *(uint4*)&Qs[r * 72 + c8 * 8] = q4;
        *(uint4*)&Ksm[r * 36 + c8 * 4] = *(const uint4*)(rp + INNERD + c8 * 8);
        *(uint4*)&Vs[r * 72 + c8 * 8] = *(const uint4*)(rp + 2 * INNERD + c8 * 8);
    }
    __syncthreads();

    const uint32_t sbQ = (uint32_t)__cvta_generic_to_shared(Qs);
    const uint32_t sbK = (uint32_t)__cvta_generic_to_shared(Ksm);
    const uint32_t sbV = (uint32_t)__cvta_generic_to_shared(Vs);

    uint32_t a[2][4][4];
#pragma unroll
    for (int mi = 0; mi < 2; mi++)
#pragma unroll
        for (int ks = 0; ks < 4; ks++)
            ldsm4(a[mi][ks],
                  sbQ + ((warp * 32 + mi * 16 + (lane & 15)) * 72
                         + ks * 16 + (lane >> 4) * 8) * 2);

    float s[2][8][4];
#pragma unroll
    for (int mi = 0; mi < 2; mi++)
#pragma unroll
        for (int ni = 0; ni < 8; ni++)
#pragma unroll
            for (int j = 0; j < 4; j++) s[mi][ni][j] = 0.f;
    const uint32_t kl = sbK + ((lane >> 4) * 8 + (lane & 7)) * 144 + ((lane >> 3) & 1) * 16;
#pragma unroll
    for (int ks = 0; ks < 4; ks++) {
#pragma unroll
        for (int p = 0; p < 4; p++) {
            uint32_t t4[4];
            ldsm4(t4, kl + p * 2304 + ks * 32);
#pragma unroll
            for (int mi = 0; mi < 2; mi++) {
                mma16(s[mi][2 * p], a[mi][ks], t4);
                mma16(s[mi][2 * p + 1], a[mi][ks], t4 + 2);
            }
        }
    }

    float inv0[2], inv1[2];
#pragma unroll
    for (int mi = 0; mi < 2; mi++) {
        float m0 = -1e30f, m1 = -1e30f;
#pragma unroll
        for (int ni = 0; ni < 8; ni++) {
            m0 = fmaxf(m0, fmaxf(s[mi][ni][0], s[mi][ni][1]));
            m1 = fmaxf(m1, fmaxf(s[mi][ni][2], s[mi][ni][3]));
        }
        m0 = fmaxf(m0, __shfl_xor_sync(0xffffffff, m0, 1));
        m0 = fmaxf(m0, __shfl_xor_sync(0xffffffff, m0, 2));
        m1 = fmaxf(m1, __shfl_xor_sync(0xffffffff, m1, 1));
        m1 = fmaxf(m1, __shfl_xor_sync(0xffffffff, m1, 2));
        float s0 = 0.f, s1 = 0.f;
#pragma unroll
        for (int ni = 0; ni < 8; ni++) {
            s[mi][ni][0] = __expf(s[mi][ni][0] - m0);
            s[mi][ni][1] = __expf(s[mi][ni][1] - m0);
            s[mi][ni][2] = __expf(s[mi][ni][2] - m1);
            s[mi][ni][3] = __expf(s[mi][ni][3] - m1);
            s0 += s[mi][ni][0] + s[mi][ni][1];
            s1 += s[mi][ni][2] + s[mi][ni][3];
        }
        s0 += __shfl_xor_sync(0xffffffff, s0, 1);
        s0 += __shfl_xor_sync(0xffffffff, s0, 2);
        s1 += __shfl_xor_sync(0xffffffff, s1, 1);
        s1 += __shfl_xor_sync(0xffffffff, s1, 2);
        inv0[mi] = 1.f / s0; inv1[mi] = 1.f / s1;
    }

    uint32_t pa[2][4][4];
#pragma unroll
    for (int mi = 0; mi < 2; mi++)
#pragma unroll
        for (int ks = 0; ks < 4; ks++) {
            pa[mi][ks][0] = h2u(__floats2half2_rn(s[mi][2 * ks][0], s[mi][2 * ks][1]));
            pa[mi][ks][1] = h2u(__floats2half2_rn(s[mi][2 * ks][2], s[mi][2 * ks][3]));
            pa[mi][ks][2] = h2u(__floats2half2_rn(s[mi][2 * ks + 1][0], s[mi][2 * ks + 1][1]));
            pa[mi][ks][3] = h2u(__floats2half2_rn(s[mi][2 * ks + 1][2], s[mi][2 * ks + 1][3]));
        }

    float o[2][8][4];
#pragma unroll
    for (int mi = 0; mi < 2; mi++)
#pragma unroll
        for (int ni = 0; ni < 8; ni++)
#pragma unroll
            for (int j = 0; j < 4; j++) o[mi][ni][j] = 0.f;
    const uint32_t vl = sbV + ((lane & 15) * 72 + (lane >> 4) * 8) * 2;
#pragma unroll
    for (int ks = 0; ks < 4; ks++) {
#pragma unroll
        for (int nd = 0; nd < 4; nd++) {
            uint32_t t4[4];
            ldsm4t(t4, vl + ks * 2304 + nd * 32);
#pragma unroll
            for (int mi = 0; mi < 2; mi++) {
                mma16(o[mi][2 * nd], pa[mi][ks], t4);
                mma16(o[mi][2 * nd + 1], pa[mi][ks], t4 + 2);
            }
        }
    }

    __half* ob = g_o + (size_t)win * 64 * INNERD + hd * 64;
#pragma unroll
    for (int mi = 0; mi < 2; mi++) {
        int r = warp * 32 + mi * 16 + (lane >> 2);
#pragma unroll
        for (int ni = 0; ni < 8; ni++) {
            int col = ni * 8 + (lane & 3) * 2;
            *(__half2*)&ob[(size_t)r * INNERD + col] =
                __floats2half2_rn(o[mi][ni][0] * inv0[mi], o[mi][ni][1] * inv0[mi]);
            *(__half2*)&ob[(size_t)(r + 8) * INNERD + col] =
                __floats2half2_rn(o[mi][ni][2] * inv1[mi], o[mi][ni][3] * inv1[mi]);
        }
    }
}

extern "C" void kernel_launch(void* const* d_in, const int* in_sizes, int n_in,
                              void* d_out, int out_size) {
    const float* x     = (const float*)d_in[0];
    const float* w_qkv = (const float*)d_in[1];
    const float* w_out = (const float*)d_in[2];
    const float* b_out = (const float*)d_in[3];
    float* out = (float*)d_out;

    cudaFuncSetAttribute(gemm_fp16_k<TOKD, QKVD, 0>,
                         cudaFuncAttributeMaxDynamicSharedMemorySize, GEMM_SMEM);
    cudaFuncSetAttribute(gemm_fp16_k<INNERD, TOKD, 1>,
                         cudaFuncAttributeMaxDynamicSharedMemorySize, GEMM_SMEM);

    perm_wqkv_k<<<dim3(TOKD / 64, QKVD / 32), dim3(32, 8)>>>(w_qkv);
    perm_wout_k<<<dim3(INNERD / 64, TOKD / 32), dim3(32, 8)>>>(w_out, b_out);
    gather_k<<<2048, 256>>>(x);
    gemm_fp16_k<TOKD, QKVD, 0>
        <<<dim3(QKVD / 128, NTOK / 128), 128, GEMM_SMEM>>>(nullptr);
    attn_k<<<dim3(8, 512), 64>>>();
    gemm_fp16_k<INNERD, TOKD, 1>
        <<<dim3(TOKD / 128, NTOK / 128), 128, GEMM_SMEM>>>(out);
}